// round 1
// baseline (speedup 1.0000x reference)
#include <cuda_runtime.h>
#include <cuda_bf16.h>
#include <math.h>

// Problem constants
#define Bsz 2
#define Hh  64
#define Ww  24
#define Cc  256
#define Pp  8
#define HP  8            // block height = H/P
#define NHh 8
#define DK  32
#define KV  4
#define NROW (Bsz*Hh*Ww)       // 3072
#define NELEM (NROW*Cc)        // 786432
#define LBLK (HP*Ww)           // 192 rows per block
#define LKEY (KV*LBLK)         // 768 keys

#define QK_SCALE (0.17677669529663687f * 1.44269504088896340f)  // 1/sqrt(32) * log2(e)

// ---------------- device scratch (no allocations allowed) ----------------
// 0:qp 1:kp 2:vp 3:kvg 4:q2 5:k2 6:v2 7:ctx 8:rout 9:xres 10:conv
__device__ float g_buf[11u * NELEM];
__device__ float g_loc[2 * 16 * Cc];   // qloc[16*256] then kloc[16*256]
__device__ int   g_R[Bsz * Pp * KV];

// ---------------- fast exp2 on FMA pipe (degree-6 Taylor) ----------------
__device__ __forceinline__ float fast_exp2(float x) {
    x = fmaxf(x, -126.0f);
    float fl = floorf(x);
    float f  = x - fl;                       // [0,1)
    float p  = 1.5403530393381609e-4f;
    p = fmaf(p, f, 1.3333558146428443e-3f);
    p = fmaf(p, f, 9.6181291076284772e-3f);
    p = fmaf(p, f, 5.5504108664821580e-2f);
    p = fmaf(p, f, 2.4022650695910072e-1f);
    p = fmaf(p, f, 6.9314718055994531e-1f);
    p = fmaf(p, f, 1.0f);                    // 2^f in [1,2)
    int ei = (int)fl;
    return __int_as_float(__float_as_int(p) + (ei << 23));
}

// ---------------- generic tiled GEMM: C = A(MxK) @ B(KxN) + bias ----------------
// IM2COL=true: A is interpreted as 5x5 SAME conv patches over [B,H,W,C] input.
#define BM 64
#define BN 64
#define BK 16

template<bool IM2COL>
__global__ void gemm_bias_kernel(const float* __restrict__ A,
                                 const float* __restrict__ Bm,
                                 const float* __restrict__ bias,
                                 float* __restrict__ C,
                                 int M, int N, int K)
{
    __shared__ float As[BK][BM];
    __shared__ float Bs[BK][BN];
    const int tid = threadIdx.x;
    const int m0 = blockIdx.x * BM;
    const int n0 = blockIdx.y * BN;
    const int ty = tid >> 4;          // 0..15
    const int tx = tid & 15;          // 0..15

    // A loader: thread loads 4 consecutive k for one m
    const int a_mm = tid >> 2;        // 0..63
    const int a_kk = (tid & 3) * 4;   // 0,4,8,12
    // B loader: thread loads 4 consecutive n for one k
    const int b_kk = tid >> 4;        // 0..15
    const int b_nn = (tid & 15) * 4;

    float acc[4][4];
#pragma unroll
    for (int i = 0; i < 4; i++)
#pragma unroll
        for (int j = 0; j < 4; j++) acc[i][j] = 0.f;

    for (int k0 = 0; k0 < K; k0 += BK) {
        float4 av;
        if (!IM2COL) {
            av = *(const float4*)&A[(long)(m0 + a_mm) * K + k0 + a_kk];
        } else {
            const int m  = m0 + a_mm;
            const int b  = m / (Hh * Ww);
            const int h  = (m / Ww) % Hh;
            const int w  = m % Ww;
            const int k  = k0 + a_kk;
            const int kh = k / (5 * Cc);
            const int kw = (k / Cc) % 5;
            const int ci = k % Cc;           // 4 consecutive cin stay in-row (256%16==0)
            const int hh = h + kh - 2;
            const int ww = w + kw - 2;
            if (hh >= 0 && hh < Hh && ww >= 0 && ww < Ww)
                av = *(const float4*)&A[(((long)b * Hh + hh) * Ww + ww) * Cc + ci];
            else
                av = make_float4(0.f, 0.f, 0.f, 0.f);
        }
        As[a_kk + 0][a_mm] = av.x;
        As[a_kk + 1][a_mm] = av.y;
        As[a_kk + 2][a_mm] = av.z;
        As[a_kk + 3][a_mm] = av.w;

        float4 bv = *(const float4*)&Bm[(long)(k0 + b_kk) * N + n0 + b_nn];
        *(float4*)&Bs[b_kk][b_nn] = bv;

        __syncthreads();
#pragma unroll
        for (int kk = 0; kk < BK; kk++) {
            float ar[4], br[4];
#pragma unroll
            for (int i = 0; i < 4; i++) ar[i] = As[kk][ty * 4 + i];
#pragma unroll
            for (int j = 0; j < 4; j++) br[j] = Bs[kk][tx * 4 + j];
#pragma unroll
            for (int i = 0; i < 4; i++)
#pragma unroll
                for (int j = 0; j < 4; j++)
                    acc[i][j] = fmaf(ar[i], br[j], acc[i][j]);
        }
        __syncthreads();
    }

#pragma unroll
    for (int i = 0; i < 4; i++) {
        const long row = m0 + ty * 4 + i;
#pragma unroll
        for (int j = 0; j < 4; j++) {
            const int col = n0 + tx * 4 + j;
            C[row * N + col] = acc[i][j] + bias[col];
        }
    }
}

// ---------------- elementwise add ----------------
__global__ void add_kernel(const float* __restrict__ a, const float* __restrict__ b,
                           float* __restrict__ c, int n)
{
    int i = blockIdx.x * blockDim.x + threadIdx.x;
    if (i < n) c[i] = a[i] + b[i];
}

// ---------------- block mean pooling: q_loc/k_loc [16,256] ----------------
__global__ void pool_kernel(const float* __restrict__ qp, const float* __restrict__ kp,
                            float* __restrict__ qloc, float* __restrict__ kloc)
{
    const int bp = blockIdx.x;        // 0..15
    const int c  = threadIdx.x;       // 0..255
    const float* qb = qp + (long)bp * LBLK * Cc + c;
    const float* kb = kp + (long)bp * LBLK * Cc + c;
    float sq = 0.f, sk = 0.f;
    for (int i = 0; i < LBLK; i++) {
        sq += qb[i * Cc];
        sk += kb[i * Cc];
    }
    qloc[bp * Cc + c] = sq * (1.f / (float)LBLK);
    kloc[bp * Cc + c] = sk * (1.f / (float)LBLK);
}

// ---------------- routing: S_loc + top-4 per (b,p) ----------------
__global__ void route_kernel(const float* __restrict__ qloc, const float* __restrict__ kloc,
                             int* __restrict__ R)
{
    const int bp = blockIdx.x;         // b*8+p
    const int b  = bp / Pp;
    const int warp = threadIdx.x >> 5;
    const int lane = threadIdx.x & 31;
    __shared__ float s[8];
    const float* q = qloc + bp * Cc;
    const float* k = kloc + (b * Pp + warp) * Cc;
    float partial = 0.f;
    for (int c = lane; c < Cc; c += 32) partial += q[c] * k[c];
#pragma unroll
    for (int o = 16; o; o >>= 1) partial += __shfl_xor_sync(0xffffffff, partial, o);
    if (lane == 0) s[warp] = partial;
    __syncthreads();
    if (threadIdx.x == 0) {
        bool used[8] = {};
        for (int t = 0; t < KV; t++) {
            int best = 0; float bv = -1e30f;
            for (int j = 0; j < Pp; j++)
                if (!used[j] && s[j] > bv) { bv = s[j]; best = j; }
            used[best] = true;
            R[bp * KV + t] = best;
        }
    }
}

// ---------------- attention: per (b,p,h), Q[192,32] vs gathered K/V[768,32] ----------------
#define KCHUNK 128
__global__ void attention_kernel(const float* __restrict__ q2,
                                 const float* __restrict__ k2,
                                 const float* __restrict__ v2,
                                 const int* __restrict__ R,
                                 float* __restrict__ ctx)
{
    __shared__ float Ks[KCHUNK * DK];
    __shared__ float Vs[KCHUNK * DK];
    __shared__ int   Rs[KV];

    const int blk = blockIdx.x;        // b*64 + p*8 + h
    const int h = blk % NHh;
    const int p = (blk / NHh) % Pp;
    const int b = blk / (NHh * Pp);
    const int tid = threadIdx.x;

    if (tid < KV) Rs[tid] = R[(b * Pp + p) * KV + tid];

    const bool active = (tid < LBLK);
    float qv[DK], acc[DK];
    float m = -1e30f, l = 0.f;
    if (active) {
        const float* qrow = q2 + ((long)((b * Pp + p) * LBLK + tid)) * Cc + h * DK;
#pragma unroll
        for (int d = 0; d < DK; d++) { qv[d] = qrow[d] * QK_SCALE; acc[d] = 0.f; }
    }

    for (int ch = 0; ch < LKEY / KCHUNK; ch++) {
        __syncthreads();
        const int kg0 = ch * KCHUNK;
        // load 128 keys' K and V rows (float4 per thread iteration)
        for (int i = tid; i < KCHUNK * (DK / 4); i += blockDim.x) {
            const int row = i >> 3;
            const int d4  = (i & 7) * 4;
            const int kg  = kg0 + row;
            const int ks  = kg / LBLK;
            const int rr  = kg - ks * LBLK;
            const int r   = Rs[ks];
            const long base = ((long)(b * Pp + r) * LBLK + rr) * Cc + h * DK + d4;
            *(float4*)&Ks[row * DK + d4] = *(const float4*)&k2[base];
            *(float4*)&Vs[row * DK + d4] = *(const float4*)&v2[base];
        }
        __syncthreads();
        if (active) {
            for (int k = 0; k < KCHUNK; k++) {
                const float* kr = &Ks[k * DK];
                float s0 = 0.f, s1 = 0.f, s2 = 0.f, s3 = 0.f;
#pragma unroll
                for (int d = 0; d < DK; d += 4) {
                    s0 = fmaf(qv[d + 0], kr[d + 0], s0);
                    s1 = fmaf(qv[d + 1], kr[d + 1], s1);
                    s2 = fmaf(qv[d + 2], kr[d + 2], s2);
                    s3 = fmaf(qv[d + 3], kr[d + 3], s3);
                }
                const float s = (s0 + s1) + (s2 + s3);
                const float mnew = fmaxf(m, s);
                const float corr = fast_exp2(m - mnew);
                const float pe   = fast_exp2(s - mnew);
                l = fmaf(l, corr, pe);
                const float* vr = &Vs[k * DK];
#pragma unroll
                for (int d = 0; d < DK; d++)
                    acc[d] = fmaf(acc[d], corr, pe * vr[d]);
                m = mnew;
            }
        }
    }

    if (active) {
        const float inv = 1.0f / l;
        float* orow = ctx + ((long)((b * Pp + p) * LBLK + tid)) * Cc + h * DK;
#pragma unroll
        for (int d = 0; d < DK; d++) orow[d] = acc[d] * inv;
    }
}

// ---------------- fused residual add + LayerNorm ----------------
__global__ void add_ln_kernel(const float* __restrict__ a, const float* __restrict__ bsrc,
                              const float* __restrict__ g, const float* __restrict__ beta,
                              float* __restrict__ out)
{
    const int mrow = blockIdx.x;
    const int c = threadIdx.x;
    __shared__ float red[Cc];
    const float v = a[(long)mrow * Cc + c] + bsrc[(long)mrow * Cc + c];
    red[c] = v;
    __syncthreads();
    for (int s = Cc / 2; s > 0; s >>= 1) {
        if (c < s) red[c] += red[c + s];
        __syncthreads();
    }
    const float mean = red[0] * (1.f / (float)Cc);
    __syncthreads();
    const float d = v - mean;
    red[c] = d * d;
    __syncthreads();
    for (int s = Cc / 2; s > 0; s >>= 1) {
        if (c < s) red[c] += red[c + s];
        __syncthreads();
    }
    const float var = red[0] * (1.f / (float)Cc);
    out[(long)mrow * Cc + c] = d * rsqrtf(var + 1e-5f) * g[c] + beta[c];
}

// ---------------- launcher ----------------
extern "C" void kernel_launch(void* const* d_in, const int* in_sizes, int n_in,
                              void* d_out, int out_size)
{
    const float* x        = (const float*)d_in[0];
    const float* wq_proj  = (const float*)d_in[1];
    const float* bq_proj  = (const float*)d_in[2];
    const float* wk_proj  = (const float*)d_in[3];
    const float* bk_proj  = (const float*)d_in[4];
    const float* wv_proj  = (const float*)d_in[5];
    const float* bv_proj  = (const float*)d_in[6];
    const float* wq_a     = (const float*)d_in[7];
    const float* bq_a     = (const float*)d_in[8];
    const float* wk_a     = (const float*)d_in[9];
    const float* bk_a     = (const float*)d_in[10];
    const float* wv_a     = (const float*)d_in[11];
    const float* bv_a     = (const float*)d_in[12];
    const float* wo_a     = (const float*)d_in[13];
    const float* bo_a     = (const float*)d_in[14];
    const float* conv_w   = (const float*)d_in[15];
    const float* conv_b   = (const float*)d_in[16];
    const float* ln1_g    = (const float*)d_in[17];
    const float* ln1_b    = (const float*)d_in[18];
    const float* ln2_g    = (const float*)d_in[19];
    const float* ln2_b    = (const float*)d_in[20];
    float* out = (float*)d_out;

    float* buf = nullptr;
    cudaGetSymbolAddress((void**)&buf, g_buf);
    float* loc = nullptr;
    cudaGetSymbolAddress((void**)&loc, g_loc);
    int* Rp = nullptr;
    cudaGetSymbolAddress((void**)&Rp, g_R);

    float* qp   = buf + 0l  * NELEM;
    float* kp   = buf + 1l  * NELEM;
    float* vp   = buf + 2l  * NELEM;
    float* kvg  = buf + 3l  * NELEM;
    float* q2   = buf + 4l  * NELEM;
    float* k2   = buf + 5l  * NELEM;
    float* v2   = buf + 6l  * NELEM;
    float* ctx  = buf + 7l  * NELEM;
    float* rout = buf + 8l  * NELEM;
    float* xres = buf + 9l  * NELEM;
    float* cnv  = buf + 10l * NELEM;
    float* qloc = loc;
    float* kloc = loc + 16 * Cc;

    const dim3 ggrid(NROW / BM, Cc / BN);   // (48,4)
    const dim3 gblk(256);

    // block projections
    gemm_bias_kernel<false><<<ggrid, gblk>>>(x, wq_proj, bq_proj, qp, NROW, Cc, Cc);
    gemm_bias_kernel<false><<<ggrid, gblk>>>(x, wk_proj, bk_proj, kp, NROW, Cc, Cc);
    gemm_bias_kernel<false><<<ggrid, gblk>>>(x, wv_proj, bv_proj, vp, NROW, Cc, Cc);

    // conv input = k_p + v_p
    add_kernel<<<NELEM / 256, 256>>>(kp, vp, kvg, NELEM);

    // routing
    pool_kernel<<<Bsz * Pp, Cc>>>(qp, kp, qloc, kloc);
    route_kernel<<<Bsz * Pp, 256>>>(qloc, kloc, Rp);

    // attention head projections (gather commutes with elementwise projection)
    gemm_bias_kernel<false><<<ggrid, gblk>>>(qp, wq_a, bq_a, q2, NROW, Cc, Cc);
    gemm_bias_kernel<false><<<ggrid, gblk>>>(kp, wk_a, bk_a, k2, NROW, Cc, Cc);
    gemm_bias_kernel<false><<<ggrid, gblk>>>(vp, wv_a, bv_a, v2, NROW, Cc, Cc);

    // routed attention (kv-mean is identity since queries are replicated)
    attention_kernel<<<Bsz * Pp * NHh, 256>>>(q2, k2, v2, Rp, ctx);

    // output projection
    gemm_bias_kernel<false><<<ggrid, gblk>>>(ctx, wo_a, bo_a, rout, NROW, Cc, Cc);

    // 5x5 SAME conv as implicit GEMM over kvg
    gemm_bias_kernel<true><<<ggrid, gblk>>>(kvg, conv_w, conv_b, cnv, NROW, Cc, 5 * 5 * Cc);

    // LN(x + routing_out), then LN(x_res + conv)
    add_ln_kernel<<<NROW, Cc>>>(x, rout, ln1_g, ln1_b, xres);
    add_ln_kernel<<<NROW, Cc>>>(xres, cnv, ln2_g, ln2_b, out);
}

// round 2
// speedup vs baseline: 1.4771x; 1.4771x over previous
#include <cuda_runtime.h>
#include <cuda_bf16.h>
#include <math.h>

// Problem constants
#define Bsz 2
#define Hh  64
#define Ww  24
#define Cc  256
#define Pp  8
#define HP  8
#define NHh 8
#define DK  32
#define KV  4
#define NROW (Bsz*Hh*Ww)       // 3072
#define NELEM (NROW*Cc)        // 786432
#define LBLK (HP*Ww)           // 192
#define LKEY (KV*LBLK)         // 768

#define QK_SCALE (0.17677669529663687f * 1.44269504088896340f)  // 1/sqrt(32)*log2(e)

// ---------------- device scratch ----------------
// 0:qp 1:kp 2:vp 3:kvg 4:q2 5:k2 6:v2 7:ctx 8:rout 9:xres 10..12:conv partials
__device__ float g_buf[13u * NELEM];
__device__ float g_loc[2 * 16 * Cc];
__device__ int   g_R[Bsz * Pp * KV];

// ---------------- packed f32x2 helpers (sm_103a) ----------------
__device__ __forceinline__ unsigned long long pk2(float lo, float hi) {
    unsigned long long r;
    asm("mov.b64 %0, {%1, %2};" : "=l"(r)
        : "r"(__float_as_uint(lo)), "r"(__float_as_uint(hi)));
    return r;
}
__device__ __forceinline__ unsigned long long ffma2(unsigned long long a,
                                                    unsigned long long b,
                                                    unsigned long long c) {
    unsigned long long d;
    asm("fma.rn.f32x2 %0, %1, %2, %3;" : "=l"(d) : "l"(a), "l"(b), "l"(c));
    return d;
}
__device__ __forceinline__ unsigned long long fmul2(unsigned long long a,
                                                    unsigned long long b) {
    unsigned long long d;
    asm("mul.rn.f32x2 %0, %1, %2;" : "=l"(d) : "l"(a), "l"(b));
    return d;
}
__device__ __forceinline__ float2 upk2(unsigned long long v) {
    unsigned int lo, hi;
    asm("mov.b64 {%0, %1}, %2;" : "=r"(lo), "=r"(hi) : "l"(v));
    return make_float2(__uint_as_float(lo), __uint_as_float(hi));
}

// ---------------- fast exp2 on FMA pipe ----------------
__device__ __forceinline__ float fast_exp2(float x) {
    x = fmaxf(x, -126.0f);
    float fl = floorf(x);
    float f  = x - fl;
    float p  = 1.5403530393381609e-4f;
    p = fmaf(p, f, 1.3333558146428443e-3f);
    p = fmaf(p, f, 9.6181291076284772e-3f);
    p = fmaf(p, f, 5.5504108664821580e-2f);
    p = fmaf(p, f, 2.4022650695910072e-1f);
    p = fmaf(p, f, 6.9314718055994531e-1f);
    p = fmaf(p, f, 1.0f);
    return __int_as_float(__float_as_int(p) + ((int)fl << 23));
}

// ---------------- fused triple GEMM (select by blockIdx.z) ----------------
#define BM 64
#define BN 64
#define BK 16

struct GemmSet {
    const float* A[3];
    const float* B[3];
    const float* bias[3];
    float*       C[3];
};

__global__ void gemm3_kernel(GemmSet gs)   // M=NROW, N=Cc, K=Cc
{
    __shared__ float As[BK][BM];
    __shared__ float Bs[BK][BN];
    const int z = blockIdx.z;
    const float* __restrict__ A    = gs.A[z];
    const float* __restrict__ Bm   = gs.B[z];
    const float* __restrict__ bias = gs.bias[z];
    float* __restrict__ C          = gs.C[z];

    const int tid = threadIdx.x;
    const int m0 = blockIdx.x * BM;
    const int n0 = blockIdx.y * BN;
    const int ty = tid >> 4;
    const int tx = tid & 15;
    const int a_mm = tid >> 2;
    const int a_kk = (tid & 3) * 4;
    const int b_kk = tid >> 4;
    const int b_nn = (tid & 15) * 4;

    unsigned long long acc2[4][2];
#pragma unroll
    for (int i = 0; i < 4; i++) { acc2[i][0] = 0ull; acc2[i][1] = 0ull; }

    for (int k0 = 0; k0 < Cc; k0 += BK) {
        float4 av = *(const float4*)&A[(long)(m0 + a_mm) * Cc + k0 + a_kk];
        As[a_kk + 0][a_mm] = av.x;
        As[a_kk + 1][a_mm] = av.y;
        As[a_kk + 2][a_mm] = av.z;
        As[a_kk + 3][a_mm] = av.w;
        *(float4*)&Bs[b_kk][b_nn] = *(const float4*)&Bm[(long)(k0 + b_kk) * Cc + n0 + b_nn];
        __syncthreads();
#pragma unroll
        for (int kk = 0; kk < BK; kk++) {
            const float4 a4 = *(const float4*)&As[kk][ty * 4];
            const ulonglong2 b2 = *(const ulonglong2*)&Bs[kk][tx * 4];
            unsigned long long p0 = pk2(a4.x, a4.x);
            unsigned long long p1 = pk2(a4.y, a4.y);
            unsigned long long p2 = pk2(a4.z, a4.z);
            unsigned long long p3 = pk2(a4.w, a4.w);
            acc2[0][0] = ffma2(p0, b2.x, acc2[0][0]);
            acc2[0][1] = ffma2(p0, b2.y, acc2[0][1]);
            acc2[1][0] = ffma2(p1, b2.x, acc2[1][0]);
            acc2[1][1] = ffma2(p1, b2.y, acc2[1][1]);
            acc2[2][0] = ffma2(p2, b2.x, acc2[2][0]);
            acc2[2][1] = ffma2(p2, b2.y, acc2[2][1]);
            acc2[3][0] = ffma2(p3, b2.x, acc2[3][0]);
            acc2[3][1] = ffma2(p3, b2.y, acc2[3][1]);
        }
        __syncthreads();
    }

    const float4 bi = *(const float4*)&bias[n0 + tx * 4];
#pragma unroll
    for (int i = 0; i < 4; i++) {
        const long row = m0 + ty * 4 + i;
        float2 f0 = upk2(acc2[i][0]);
        float2 f1 = upk2(acc2[i][1]);
        float4 outv = make_float4(f0.x + bi.x, f0.y + bi.y, f1.x + bi.z, f1.y + bi.w);
        *(float4*)&C[row * Cc + n0 + tx * 4] = outv;
    }
}

// ---------------- conv implicit GEMM, split-K=3 over blockIdx.z ----------------
__global__ void conv_gemm_kernel(const float* __restrict__ A,
                                 const float* __restrict__ Bm,
                                 float* __restrict__ Cbase)
{
    __shared__ float As[BK][BM];
    __shared__ float Bs[BK][BN];
    const int z = blockIdx.z;
    const int kbeg = (z == 0) ? 0 : (z == 1 ? 2304 : 4352);
    const int kend = (z == 0) ? 2304 : (z == 1 ? 4352 : 6400);
    float* __restrict__ C = Cbase + (long)z * NELEM;

    const int tid = threadIdx.x;
    const int m0 = blockIdx.x * BM;
    const int n0 = blockIdx.y * BN;
    const int ty = tid >> 4;
    const int tx = tid & 15;
    const int a_mm = tid >> 2;
    const int a_kk = (tid & 3) * 4;
    const int b_kk = tid >> 4;
    const int b_nn = (tid & 15) * 4;

    // precompute im2col coordinates for this thread's A row
    const int m = m0 + a_mm;
    const int b = m / (Hh * Ww);
    const int h = (m / Ww) % Hh;
    const int w = m % Ww;

    unsigned long long acc2[4][2];
#pragma unroll
    for (int i = 0; i < 4; i++) { acc2[i][0] = 0ull; acc2[i][1] = 0ull; }

    for (int k0 = kbeg; k0 < kend; k0 += BK) {
        const int k  = k0 + a_kk;
        const int kh = k / (5 * Cc);
        const int kw = (k / Cc) % 5;
        const int ci = k % Cc;
        const int hh = h + kh - 2;
        const int ww = w + kw - 2;
        float4 av;
        if (hh >= 0 && hh < Hh && ww >= 0 && ww < Ww)
            av = *(const float4*)&A[(((long)b * Hh + hh) * Ww + ww) * Cc + ci];
        else
            av = make_float4(0.f, 0.f, 0.f, 0.f);
        As[a_kk + 0][a_mm] = av.x;
        As[a_kk + 1][a_mm] = av.y;
        As[a_kk + 2][a_mm] = av.z;
        As[a_kk + 3][a_mm] = av.w;
        *(float4*)&Bs[b_kk][b_nn] = *(const float4*)&Bm[(long)(k0 + b_kk) * Cc + n0 + b_nn];
        __syncthreads();
#pragma unroll
        for (int kk = 0; kk < BK; kk++) {
            const float4 a4 = *(const float4*)&As[kk][ty * 4];
            const ulonglong2 b2 = *(const ulonglong2*)&Bs[kk][tx * 4];
            unsigned long long p0 = pk2(a4.x, a4.x);
            unsigned long long p1 = pk2(a4.y, a4.y);
            unsigned long long p2 = pk2(a4.z, a4.z);
            unsigned long long p3 = pk2(a4.w, a4.w);
            acc2[0][0] = ffma2(p0, b2.x, acc2[0][0]);
            acc2[0][1] = ffma2(p0, b2.y, acc2[0][1]);
            acc2[1][0] = ffma2(p1, b2.x, acc2[1][0]);
            acc2[1][1] = ffma2(p1, b2.y, acc2[1][1]);
            acc2[2][0] = ffma2(p2, b2.x, acc2[2][0]);
            acc2[2][1] = ffma2(p2, b2.y, acc2[2][1]);
            acc2[3][0] = ffma2(p3, b2.x, acc2[3][0]);
            acc2[3][1] = ffma2(p3, b2.y, acc2[3][1]);
        }
        __syncthreads();
    }

#pragma unroll
    for (int i = 0; i < 4; i++) {
        const long row = m0 + ty * 4 + i;
        float2 f0 = upk2(acc2[i][0]);
        float2 f1 = upk2(acc2[i][1]);
        *(float4*)&C[row * Cc + n0 + tx * 4] = make_float4(f0.x, f0.y, f1.x, f1.y);
    }
}

// ---------------- elementwise add ----------------
__global__ void add_kernel(const float* __restrict__ a, const float* __restrict__ b,
                           float* __restrict__ c, int n)
{
    int i = blockIdx.x * blockDim.x + threadIdx.x;
    if (i < n) c[i] = a[i] + b[i];
}

// ---------------- block mean pooling ----------------
__global__ void pool_kernel(const float* __restrict__ qp, const float* __restrict__ kp,
                            float* __restrict__ qloc, float* __restrict__ kloc)
{
    const int bp = blockIdx.x;
    const int c  = threadIdx.x;
    const float* qb = qp + (long)bp * LBLK * Cc + c;
    const float* kb = kp + (long)bp * LBLK * Cc + c;
    float sq = 0.f, sk = 0.f;
    for (int i = 0; i < LBLK; i++) { sq += qb[i * Cc]; sk += kb[i * Cc]; }
    qloc[bp * Cc + c] = sq * (1.f / (float)LBLK);
    kloc[bp * Cc + c] = sk * (1.f / (float)LBLK);
}

// ---------------- routing ----------------
__global__ void route_kernel(const float* __restrict__ qloc, const float* __restrict__ kloc,
                             int* __restrict__ R)
{
    const int bp = blockIdx.x;
    const int b  = bp / Pp;
    const int warp = threadIdx.x >> 5;
    const int lane = threadIdx.x & 31;
    __shared__ float s[8];
    const float* q = qloc + bp * Cc;
    const float* k = kloc + (b * Pp + warp) * Cc;
    float partial = 0.f;
    for (int c = lane; c < Cc; c += 32) partial += q[c] * k[c];
#pragma unroll
    for (int o = 16; o; o >>= 1) partial += __shfl_xor_sync(0xffffffff, partial, o);
    if (lane == 0) s[warp] = partial;
    __syncthreads();
    if (threadIdx.x == 0) {
        bool used[8] = {};
        for (int t = 0; t < KV; t++) {
            int best = 0; float bv = -1e30f;
            for (int j = 0; j < Pp; j++)
                if (!used[j] && s[j] > bv) { bv = s[j]; best = j; }
            used[best] = true;
            R[bp * KV + t] = best;
        }
    }
}

// ---------------- attention ----------------
#define KCHUNK 128
__global__ void attention_kernel(const float* __restrict__ q2,
                                 const float* __restrict__ k2,
                                 const float* __restrict__ v2,
                                 const int* __restrict__ R,
                                 float* __restrict__ ctx)
{
    __shared__ float Ks[KCHUNK * DK];
    __shared__ float Vs[KCHUNK * DK];
    __shared__ int   Rs[KV];

    const int blk = blockIdx.x;
    const int h = blk % NHh;
    const int p = (blk / NHh) % Pp;
    const int b = blk / (NHh * Pp);
    const int tid = threadIdx.x;

    if (tid < KV) Rs[tid] = R[(b * Pp + p) * KV + tid];

    const bool active = (tid < LBLK);
    unsigned long long qv2[DK / 2], acc2[DK / 2];
    float m = -1e30f, l = 0.f;
    if (active) {
        const float* qrow = q2 + ((long)((b * Pp + p) * LBLK + tid)) * Cc + h * DK;
#pragma unroll
        for (int d2 = 0; d2 < DK / 2; d2++) {
            qv2[d2] = pk2(qrow[2 * d2] * QK_SCALE, qrow[2 * d2 + 1] * QK_SCALE);
            acc2[d2] = 0ull;
        }
    }

    for (int ch = 0; ch < LKEY / KCHUNK; ch++) {
        __syncthreads();
        const int kg0 = ch * KCHUNK;
        for (int i = tid; i < KCHUNK * (DK / 4); i += blockDim.x) {
            const int row = i >> 3;
            const int d4  = (i & 7) * 4;
            const int kg  = kg0 + row;
            const int ks  = kg / LBLK;
            const int rr  = kg - ks * LBLK;
            const int r   = Rs[ks];
            const long base = ((long)(b * Pp + r) * LBLK + rr) * Cc + h * DK + d4;
            *(float4*)&Ks[row * DK + d4] = *(const float4*)&k2[base];
            *(float4*)&Vs[row * DK + d4] = *(const float4*)&v2[base];
        }
        __syncthreads();
        if (active) {
            for (int k = 0; k < KCHUNK; k++) {
                const unsigned long long* kr = (const unsigned long long*)&Ks[k * DK];
                unsigned long long s0 = 0ull, s1 = 0ull, s2 = 0ull, s3 = 0ull;
#pragma unroll
                for (int d2 = 0; d2 < DK / 2; d2 += 4) {
                    s0 = ffma2(qv2[d2 + 0], kr[d2 + 0], s0);
                    s1 = ffma2(qv2[d2 + 1], kr[d2 + 1], s1);
                    s2 = ffma2(qv2[d2 + 2], kr[d2 + 2], s2);
                    s3 = ffma2(qv2[d2 + 3], kr[d2 + 3], s3);
                }
                const float2 f0 = upk2(s0), f1 = upk2(s1), f2 = upk2(s2), f3 = upk2(s3);
                const float s = ((f0.x + f0.y) + (f1.x + f1.y)) + ((f2.x + f2.y) + (f3.x + f3.y));
                const float mnew = fmaxf(m, s);
                const float corr = fast_exp2(m - mnew);
                const float pe   = fast_exp2(s - mnew);
                l = fmaf(l, corr, pe);
                const unsigned long long cc = pk2(corr, corr);
                const unsigned long long pp = pk2(pe, pe);
                const unsigned long long* vr = (const unsigned long long*)&Vs[k * DK];
#pragma unroll
                for (int d2 = 0; d2 < DK / 2; d2++)
                    acc2[d2] = ffma2(acc2[d2], cc, fmul2(pp, vr[d2]));
                m = mnew;
            }
        }
    }

    if (active) {
        const float inv = 1.0f / l;
        float* orow = ctx + ((long)((b * Pp + p) * LBLK + tid)) * Cc + h * DK;
#pragma unroll
        for (int d2 = 0; d2 < DK / 2; d2++) {
            float2 f = upk2(acc2[d2]);
            orow[2 * d2]     = f.x * inv;
            orow[2 * d2 + 1] = f.y * inv;
        }
    }
}

// ---------------- fused residual add + LayerNorm ----------------
__global__ void add_ln_kernel(const float* __restrict__ a, const float* __restrict__ bsrc,
                              const float* __restrict__ g, const float* __restrict__ beta,
                              float* __restrict__ out)
{
    const int mrow = blockIdx.x;
    const int c = threadIdx.x;
    __shared__ float red[Cc];
    const float v = a[(long)mrow * Cc + c] + bsrc[(long)mrow * Cc + c];
    red[c] = v;
    __syncthreads();
    for (int s = Cc / 2; s > 0; s >>= 1) {
        if (c < s) red[c] += red[c + s];
        __syncthreads();
    }
    const float mean = red[0] * (1.f / (float)Cc);
    __syncthreads();
    const float d = v - mean;
    red[c] = d * d;
    __syncthreads();
    for (int s = Cc / 2; s > 0; s >>= 1) {
        if (c < s) red[c] += red[c + s];
        __syncthreads();
    }
    const float var = red[0] * (1.f / (float)Cc);
    out[(long)mrow * Cc + c] = d * rsqrtf(var + 1e-5f) * g[c] + beta[c];
}

// xres + (p0+p1+p2+conv_bias) -> LN -> out
__global__ void add_ln4_kernel(const float* __restrict__ a, const float* __restrict__ pbase,
                               const float* __restrict__ cb,
                               const float* __restrict__ g, const float* __restrict__ beta,
                               float* __restrict__ out)
{
    const int mrow = blockIdx.x;
    const int c = threadIdx.x;
    __shared__ float red[Cc];
    const long off = (long)mrow * Cc + c;
    const float v = a[off] + pbase[off] + pbase[off + (long)NELEM] +
                    pbase[off + 2l * NELEM] + cb[c];
    red[c] = v;
    __syncthreads();
    for (int s = Cc / 2; s > 0; s >>= 1) {
        if (c < s) red[c] += red[c + s];
        __syncthreads();
    }
    const float mean = red[0] * (1.f / (float)Cc);
    __syncthreads();
    const float d = v - mean;
    red[c] = d * d;
    __syncthreads();
    for (int s = Cc / 2; s > 0; s >>= 1) {
        if (c < s) red[c] += red[c + s];
        __syncthreads();
    }
    const float var = red[0] * (1.f / (float)Cc);
    out[off] = d * rsqrtf(var + 1e-5f) * g[c] + beta[c];
}

// ---------------- launcher ----------------
extern "C" void kernel_launch(void* const* d_in, const int* in_sizes, int n_in,
                              void* d_out, int out_size)
{
    const float* x        = (const float*)d_in[0];
    const float* wq_proj  = (const float*)d_in[1];
    const float* bq_proj  = (const float*)d_in[2];
    const float* wk_proj  = (const float*)d_in[3];
    const float* bk_proj  = (const float*)d_in[4];
    const float* wv_proj  = (const float*)d_in[5];
    const float* bv_proj  = (const float*)d_in[6];
    const float* wq_a     = (const float*)d_in[7];
    const float* bq_a     = (const float*)d_in[8];
    const float* wk_a     = (const float*)d_in[9];
    const float* bk_a     = (const float*)d_in[10];
    const float* wv_a     = (const float*)d_in[11];
    const float* bv_a     = (const float*)d_in[12];
    const float* wo_a     = (const float*)d_in[13];
    const float* bo_a     = (const float*)d_in[14];
    const float* conv_w   = (const float*)d_in[15];
    const float* conv_b   = (const float*)d_in[16];
    const float* ln1_g    = (const float*)d_in[17];
    const float* ln1_b    = (const float*)d_in[18];
    const float* ln2_g    = (const float*)d_in[19];
    const float* ln2_b    = (const float*)d_in[20];
    float* out = (float*)d_out;

    float* buf = nullptr;
    cudaGetSymbolAddress((void**)&buf, g_buf);
    float* loc = nullptr;
    cudaGetSymbolAddress((void**)&loc, g_loc);
    int* Rp = nullptr;
    cudaGetSymbolAddress((void**)&Rp, g_R);

    float* qp   = buf + 0l  * NELEM;
    float* kp   = buf + 1l  * NELEM;
    float* vp   = buf + 2l  * NELEM;
    float* kvg  = buf + 3l  * NELEM;
    float* q2   = buf + 4l  * NELEM;
    float* k2   = buf + 5l  * NELEM;
    float* v2   = buf + 6l  * NELEM;
    float* ctx  = buf + 7l  * NELEM;
    float* rout = buf + 8l  * NELEM;
    float* xres = buf + 9l  * NELEM;
    float* cnvp = buf + 10l * NELEM;   // 3 partials
    float* qloc = loc;
    float* kloc = loc + 16 * Cc;

    const dim3 gblk(256);

    // fused q/k/v block projections (576 CTAs, one launch)
    {
        GemmSet gs;
        gs.A[0] = x;        gs.A[1] = x;        gs.A[2] = x;
        gs.B[0] = wq_proj;  gs.B[1] = wk_proj;  gs.B[2] = wv_proj;
        gs.bias[0] = bq_proj; gs.bias[1] = bk_proj; gs.bias[2] = bv_proj;
        gs.C[0] = qp;       gs.C[1] = kp;       gs.C[2] = vp;
        gemm3_kernel<<<dim3(NROW / BM, Cc / BN, 3), gblk>>>(gs);
    }

    add_kernel<<<NELEM / 256, 256>>>(kp, vp, kvg, NELEM);
    pool_kernel<<<Bsz * Pp, Cc>>>(qp, kp, qloc, kloc);
    route_kernel<<<Bsz * Pp, 256>>>(qloc, kloc, Rp);

    // fused attention head projections
    {
        GemmSet gs;
        gs.A[0] = qp;       gs.A[1] = kp;       gs.A[2] = vp;
        gs.B[0] = wq_a;     gs.B[1] = wk_a;     gs.B[2] = wv_a;
        gs.bias[0] = bq_a;  gs.bias[1] = bk_a;  gs.bias[2] = bv_a;
        gs.C[0] = q2;       gs.C[1] = k2;       gs.C[2] = v2;
        gemm3_kernel<<<dim3(NROW / BM, Cc / BN, 3), gblk>>>(gs);
    }

    attention_kernel<<<Bsz * Pp * NHh, 256>>>(q2, k2, v2, Rp, ctx);

    // output projection (single z)
    {
        GemmSet gs;
        gs.A[0] = ctx;   gs.A[1] = ctx;   gs.A[2] = ctx;
        gs.B[0] = wo_a;  gs.B[1] = wo_a;  gs.B[2] = wo_a;
        gs.bias[0] = bo_a; gs.bias[1] = bo_a; gs.bias[2] = bo_a;
        gs.C[0] = rout;  gs.C[1] = rout;  gs.C[2] = rout;
        gemm3_kernel<<<dim3(NROW / BM, Cc / BN, 1), gblk>>>(gs);
    }

    // conv as split-K=3 implicit GEMM (576 CTAs)
    conv_gemm_kernel<<<dim3(NROW / BM, Cc / BN, 3), gblk>>>(kvg, conv_w, cnvp);

    add_ln_kernel<<<NROW, Cc>>>(x, rout, ln1_g, ln1_b, xres);
    add_ln4_kernel<<<NROW, Cc>>>(xres, cnvp, conv_b, ln2_g, ln2_b, out);
}

// round 4
// speedup vs baseline: 1.8765x; 1.2704x over previous
#include <cuda_runtime.h>
#include <cuda_bf16.h>
#include <math.h>
#include <stdint.h>

// Problem constants
#define Bsz 2
#define Hh  64
#define Ww  24
#define Cc  256
#define Pp  8
#define HP  8
#define NHh 8
#define DK  32
#define KV  4
#define NROW (Bsz*Hh*Ww)       // 3072
#define NELEM (NROW*Cc)        // 786432
#define LBLK (HP*Ww)           // 192
#define LKEY (KV*LBLK)         // 768
#define KTOT (25*Cc)           // 6400 conv K
#define NSPLIT 2               // conv split-K
#define KPER (KTOT/NSPLIT)     // 3200
#define CHUNKS (KPER/64)       // 50

#define QK_SCALE (0.17677669529663687f * 1.44269504088896340f)

// ---------------- device scratch ----------------
// slots: 0:qp 1:kp 2:vp 3:xres 4:q2 5:k2 6:v2 7:ctx 8:rout 9..10: conv partials
__device__ float g_buf[11u * NELEM];
__device__ float g_loc[2 * 16 * Cc];
__device__ int   g_R[Bsz * Pp * KV];
__device__ __nv_bfloat16 g_kvg_hi[NELEM];
__device__ __nv_bfloat16 g_kvg_lo[NELEM];
__device__ __nv_bfloat16 g_wt_hi[Cc * KTOT];
__device__ __nv_bfloat16 g_wt_lo[Cc * KTOT];

// ---------------- packed f32x2 helpers ----------------
__device__ __forceinline__ unsigned long long pk2(float lo, float hi) {
    unsigned long long r;
    asm("mov.b64 %0, {%1, %2};" : "=l"(r)
        : "r"(__float_as_uint(lo)), "r"(__float_as_uint(hi)));
    return r;
}
__device__ __forceinline__ unsigned long long ffma2(unsigned long long a,
                                                    unsigned long long b,
                                                    unsigned long long c) {
    unsigned long long d;
    asm("fma.rn.f32x2 %0, %1, %2, %3;" : "=l"(d) : "l"(a), "l"(b), "l"(c));
    return d;
}
__device__ __forceinline__ unsigned long long fmul2(unsigned long long a,
                                                    unsigned long long b) {
    unsigned long long d;
    asm("mul.rn.f32x2 %0, %1, %2;" : "=l"(d) : "l"(a), "l"(b));
    return d;
}
__device__ __forceinline__ float2 upk2(unsigned long long v) {
    unsigned int lo, hi;
    asm("mov.b64 {%0, %1}, %2;" : "=r"(lo), "=r"(hi) : "l"(v));
    return make_float2(__uint_as_float(lo), __uint_as_float(hi));
}

// ---------------- fast exp2 on FMA pipe ----------------
__device__ __forceinline__ float fast_exp2(float x) {
    x = fmaxf(x, -126.0f);
    float fl = floorf(x);
    float f  = x - fl;
    float p  = 1.5403530393381609e-4f;
    p = fmaf(p, f, 1.3333558146428443e-3f);
    p = fmaf(p, f, 9.6181291076284772e-3f);
    p = fmaf(p, f, 5.5504108664821580e-2f);
    p = fmaf(p, f, 2.4022650695910072e-1f);
    p = fmaf(p, f, 6.9314718055994531e-1f);
    p = fmaf(p, f, 1.0f);
    return __int_as_float(__float_as_int(p) + ((int)fl << 23));
}

// ---------------- warp MMA helpers (base-target safe) ----------------
__device__ __forceinline__ uint32_t smem_u32(const void* p) {
    uint32_t a;
    asm("{ .reg .u64 t; cvta.to.shared.u64 t, %1; cvt.u32.u64 %0, t; }"
        : "=r"(a) : "l"(p));
    return a;
}
#define SWZ128(o) ((o) ^ (((o) >> 3) & 0x70))

__device__ __forceinline__ void ldsm4(uint32_t* r, uint32_t addr) {
    asm volatile("ldmatrix.sync.aligned.m8n8.x4.shared.b16 {%0,%1,%2,%3}, [%4];"
                 : "=r"(r[0]), "=r"(r[1]), "=r"(r[2]), "=r"(r[3]) : "r"(addr));
}
__device__ __forceinline__ void mma_bf16(float* c, const uint32_t* a, const uint32_t* b) {
    asm volatile(
        "mma.sync.aligned.m16n8k16.row.col.f32.bf16.bf16.f32 "
        "{%0,%1,%2,%3}, {%4,%5,%6,%7}, {%8,%9}, {%0,%1,%2,%3};"
        : "+f"(c[0]), "+f"(c[1]), "+f"(c[2]), "+f"(c[3])
        : "r"(a[0]), "r"(a[1]), "r"(a[2]), "r"(a[3]), "r"(b[0]), "r"(b[1]));
}

// ---------------- conv via mma.sync bf16 hi/lo split ----------------
// grid (48, 2, 2), 256 threads (8 warps). CTA tile M=64, N=128, k-chunk 64.
// static smem 48KB: A_hi[64][128B] A_lo B_hi[128][128B] B_lo (SW128 rows)
__global__ __launch_bounds__(256, 1)
void conv_mma_kernel(const __nv_bfloat16* __restrict__ a_hi,
                     const __nv_bfloat16* __restrict__ a_lo,
                     const __nv_bfloat16* __restrict__ b_hi,
                     const __nv_bfloat16* __restrict__ b_lo,
                     float* __restrict__ part)
{
    __shared__ char smem[49152];
    const uint32_t sb = smem_u32(smem);
    const uint32_t A_HI = sb, A_LO = sb + 8192, B_HI = sb + 16384, B_LO = sb + 32768;

    const int tid  = threadIdx.x;
    const int wid  = tid >> 5;
    const int lane = tid & 31;
    const int m0 = blockIdx.x * 64;
    const int n0 = blockIdx.y * 128;
    const int z  = blockIdx.z;

    const int wm = wid & 1;        // 2 m-tiles of 32
    const int wn = wid >> 1;       // 4 n-tiles of 32

    // A loader: 2 tasks/thread per buffer (64 rows x 8 segs = 512 units)
    int a_row[2], a_seg[2], a_h[2], a_w[2];
    long a_base[2];
#pragma unroll
    for (int i = 0; i < 2; i++) {
        const int idx = tid + 256 * i;
        a_row[i] = idx >> 3;
        a_seg[i] = idx & 7;
        const int m = m0 + a_row[i];
        const int b = m / (Hh * Ww);
        a_h[i] = (m / Ww) % Hh;
        a_w[i] = m % Ww;
        a_base[i] = (long)b * Hh * Ww * Cc;
    }
    // B loader: 4 tasks/thread per buffer (128 rows x 8 segs)
    const int b_row = tid >> 3;    // reused with +32*i
    const int b_seg = tid & 7;

    float acc[2][4][4];
#pragma unroll
    for (int i = 0; i < 2; i++)
#pragma unroll
        for (int j = 0; j < 4; j++)
#pragma unroll
            for (int q = 0; q < 4; q++) acc[i][j][q] = 0.f;

    for (int c = 0; c < CHUNKS; c++) {
        const int kb = z * KPER + c * 64;
        const int patch = kb >> 8;
        const int kh = patch / 5, kw = patch % 5;
        const int ci0 = kb & 255;

        __syncthreads();
        // load A hi/lo
#pragma unroll
        for (int i = 0; i < 2; i++) {
            const int hh = a_h[i] + kh - 2;
            const int ww = a_w[i] + kw - 2;
            uint4 vh = make_uint4(0, 0, 0, 0), vl = make_uint4(0, 0, 0, 0);
            if (hh >= 0 && hh < Hh && ww >= 0 && ww < Ww) {
                const long off = a_base[i] + ((long)hh * Ww + ww) * Cc + ci0 + a_seg[i] * 8;
                vh = *(const uint4*)(a_hi + off);
                vl = *(const uint4*)(a_lo + off);
            }
            const uint32_t so = SWZ128((uint32_t)(a_row[i] * 128 + a_seg[i] * 16));
            *(uint4*)(smem + so)        = vh;
            *(uint4*)(smem + 8192 + so) = vl;
        }
        // load B hi/lo
#pragma unroll
        for (int i = 0; i < 4; i++) {
            const int row = b_row + 32 * i;
            const long off = (long)(n0 + row) * KTOT + kb + b_seg * 8;
            const uint32_t so = SWZ128((uint32_t)(row * 128 + b_seg * 16));
            *(uint4*)(smem + 16384 + so) = *(const uint4*)(b_hi + off);
            *(uint4*)(smem + 32768 + so) = *(const uint4*)(b_lo + off);
        }
        __syncthreads();

#pragma unroll
        for (int kst = 0; kst < 4; kst++) {
            // A fragments (2 m16 tiles x hi/lo)
            uint32_t ahi[2][4], alo[2][4];
#pragma unroll
            for (int mh = 0; mh < 2; mh++) {
                const int tile = lane >> 3;
                const int r = lane & 7;
                const int row = wm * 32 + mh * 16 + ((tile & 1) << 3) + r;
                const int unit = kst * 2 + (tile >> 1);
                const uint32_t so = SWZ128((uint32_t)(row * 128 + unit * 16));
                ldsm4(ahi[mh], A_HI + so);
                ldsm4(alo[mh], A_LO + so);
            }
            // B fragments (4 n8 tiles via 2 x4-loads, x hi/lo)
            uint32_t bhi[4][2], blo[4][2];
#pragma unroll
            for (int ng = 0; ng < 2; ng++) {
                const int tile = lane >> 3;
                const int row = wn * 32 + ng * 16 + ((tile >> 1) << 3) + (lane & 7);
                const int unit = kst * 2 + (tile & 1);
                const uint32_t so = SWZ128((uint32_t)(row * 128 + unit * 16));
                uint32_t th[4], tl[4];
                ldsm4(th, B_HI + so);
                ldsm4(tl, B_LO + so);
                bhi[ng * 2][0] = th[0]; bhi[ng * 2][1] = th[1];
                bhi[ng * 2 + 1][0] = th[2]; bhi[ng * 2 + 1][1] = th[3];
                blo[ng * 2][0] = tl[0]; blo[ng * 2][1] = tl[1];
                blo[ng * 2 + 1][0] = tl[2]; blo[ng * 2 + 1][1] = tl[3];
            }
#pragma unroll
            for (int mh = 0; mh < 2; mh++)
#pragma unroll
                for (int nt = 0; nt < 4; nt++) {
                    mma_bf16(acc[mh][nt], ahi[mh], bhi[nt]);
                    mma_bf16(acc[mh][nt], alo[mh], bhi[nt]);
                    mma_bf16(acc[mh][nt], ahi[mh], blo[nt]);
                }
        }
    }

    // epilogue: write fp32 partials
    float* base = part + (size_t)z * NELEM;
#pragma unroll
    for (int mh = 0; mh < 2; mh++) {
        const int mrow = m0 + wm * 32 + mh * 16 + (lane >> 2);
#pragma unroll
        for (int nt = 0; nt < 4; nt++) {
            const int n = n0 + wn * 32 + nt * 8 + (lane & 3) * 2;
            *(float2*)&base[(size_t)mrow * Cc + n] =
                make_float2(acc[mh][nt][0], acc[mh][nt][1]);
            *(float2*)&base[(size_t)(mrow + 8) * Cc + n] =
                make_float2(acc[mh][nt][2], acc[mh][nt][3]);
        }
    }
}

// ---------------- decompose kvg = kp+vp into bf16 hi/lo ----------------
__global__ void decomp_kvg_kernel(const float* __restrict__ kp, const float* __restrict__ vp,
                                  __nv_bfloat16* __restrict__ hi, __nv_bfloat16* __restrict__ lo)
{
    const int i = blockIdx.x * blockDim.x + threadIdx.x;
    if (i < NELEM) {
        const float v = kp[i] + vp[i];
        const __nv_bfloat16 h = __float2bfloat16(v);
        hi[i] = h;
        lo[i] = __float2bfloat16(v - __bfloat162float(h));
    }
}

// ---------------- transpose + decompose conv weights: [6400,256] -> [256,6400] ----------------
__global__ void decomp_wt_kernel(const float* __restrict__ w,
                                 __nv_bfloat16* __restrict__ hi, __nv_bfloat16* __restrict__ lo)
{
    __shared__ float tile[32][33];
    const int k0 = blockIdx.x * 32;
    const int n0 = blockIdx.y * 32;
    const int tx = threadIdx.x, ty = threadIdx.y;   // 32 x 8
#pragma unroll
    for (int i = 0; i < 4; i++)
        tile[ty + i * 8][tx] = w[(long)(k0 + ty + i * 8) * Cc + n0 + tx];
    __syncthreads();
#pragma unroll
    for (int i = 0; i < 4; i++) {
        const float v = tile[tx][ty + i * 8];
        const __nv_bfloat16 h = __float2bfloat16(v);
        const long o = (long)(n0 + ty + i * 8) * KTOT + k0 + tx;
        hi[o] = h;
        lo[o] = __float2bfloat16(v - __bfloat162float(h));
    }
}

// ---------------- fused triple GEMM (FFMA2 SIMT) ----------------
#define BM 64
#define BN 64
#define BK 16

struct GemmSet {
    const float* A[3];
    const float* B[3];
    const float* bias[3];
    float*       C[3];
};

__global__ void gemm3_kernel(GemmSet gs)
{
    __shared__ float As[BK][BM];
    __shared__ float Bs[BK][BN];
    const int zz = blockIdx.z;
    const float* __restrict__ A    = gs.A[zz];
    const float* __restrict__ Bm   = gs.B[zz];
    const float* __restrict__ bias = gs.bias[zz];
    float* __restrict__ C          = gs.C[zz];

    const int tid = threadIdx.x;
    const int m0 = blockIdx.x * BM;
    const int n0 = blockIdx.y * BN;
    const int ty = tid >> 4;
    const int tx = tid & 15;
    const int a_mm = tid >> 2;
    const int a_kk = (tid & 3) * 4;
    const int b_kk = tid >> 4;
    const int b_nn = (tid & 15) * 4;

    unsigned long long acc2[4][2];
#pragma unroll
    for (int i = 0; i < 4; i++) { acc2[i][0] = 0ull; acc2[i][1] = 0ull; }

    for (int k0 = 0; k0 < Cc; k0 += BK) {
        float4 av = *(const float4*)&A[(long)(m0 + a_mm) * Cc + k0 + a_kk];
        As[a_kk + 0][a_mm] = av.x;
        As[a_kk + 1][a_mm] = av.y;
        As[a_kk + 2][a_mm] = av.z;
        As[a_kk + 3][a_mm] = av.w;
        *(float4*)&Bs[b_kk][b_nn] = *(const float4*)&Bm[(long)(k0 + b_kk) * Cc + n0 + b_nn];
        __syncthreads();
#pragma unroll
        for (int kk = 0; kk < BK; kk++) {
            const float4 a4 = *(const float4*)&As[kk][ty * 4];
            const ulonglong2 b2 = *(const ulonglong2*)&Bs[kk][tx * 4];
            unsigned long long p0 = pk2(a4.x, a4.x);
            unsigned long long p1 = pk2(a4.y, a4.y);
            unsigned long long p2 = pk2(a4.z, a4.z);
            unsigned long long p3 = pk2(a4.w, a4.w);
            acc2[0][0] = ffma2(p0, b2.x, acc2[0][0]);
            acc2[0][1] = ffma2(p0, b2.y, acc2[0][1]);
            acc2[1][0] = ffma2(p1, b2.x, acc2[1][0]);
            acc2[1][1] = ffma2(p1, b2.y, acc2[1][1]);
            acc2[2][0] = ffma2(p2, b2.x, acc2[2][0]);
            acc2[2][1] = ffma2(p2, b2.y, acc2[2][1]);
            acc2[3][0] = ffma2(p3, b2.x, acc2[3][0]);
            acc2[3][1] = ffma2(p3, b2.y, acc2[3][1]);
        }
        __syncthreads();
    }

    const float4 bi = *(const float4*)&bias[n0 + tx * 4];
#pragma unroll
    for (int i = 0; i < 4; i++) {
        const long row = m0 + ty * 4 + i;
        float2 f0 = upk2(acc2[i][0]);
        float2 f1 = upk2(acc2[i][1]);
        *(float4*)&C[row * Cc + n0 + tx * 4] =
            make_float4(f0.x + bi.x, f0.y + bi.y, f1.x + bi.z, f1.y + bi.w);
    }
}

// ---------------- block mean pooling ----------------
__global__ void pool_kernel(const float* __restrict__ qp, const float* __restrict__ kp,
                            float* __restrict__ qloc, float* __restrict__ kloc)
{
    const int bp = blockIdx.x;
    const int c  = threadIdx.x;
    const float* qb = qp + (long)bp * LBLK * Cc + c;
    const float* kb = kp + (long)bp * LBLK * Cc + c;
    float sq = 0.f, sk = 0.f;
    for (int i = 0; i < LBLK; i++) { sq += qb[i * Cc]; sk += kb[i * Cc]; }
    qloc[bp * Cc + c] = sq * (1.f / (float)LBLK);
    kloc[bp * Cc + c] = sk * (1.f / (float)LBLK);
}

// ---------------- routing ----------------
__global__ void route_kernel(const float* __restrict__ qloc, const float* __restrict__ kloc,
                             int* __restrict__ R)
{
    const int bp = blockIdx.x;
    const int b  = bp / Pp;
    const int warp = threadIdx.x >> 5;
    const int lane = threadIdx.x & 31;
    __shared__ float s[8];
    const float* q = qloc + bp * Cc;
    const float* k = kloc + (b * Pp + warp) * Cc;
    float partial = 0.f;
    for (int c = lane; c < Cc; c += 32) partial += q[c] * k[c];
#pragma unroll
    for (int o = 16; o; o >>= 1) partial += __shfl_xor_sync(0xffffffff, partial, o);
    if (lane == 0) s[warp] = partial;
    __syncthreads();
    if (threadIdx.x == 0) {
        bool used[8] = {};
        for (int t = 0; t < KV; t++) {
            int best = 0; float bv = -1e30f;
            for (int j = 0; j < Pp; j++)
                if (!used[j] && s[j] > bv) { bv = s[j]; best = j; }
            used[best] = true;
            R[bp * KV + t] = best;
        }
    }
}

// ---------------- attention ----------------
#define KCHUNK 128
__global__ void attention_kernel(const float* __restrict__ q2,
                                 const float* __restrict__ k2,
                                 const float* __restrict__ v2,
                                 const int* __restrict__ R,
                                 float* __restrict__ ctx)
{
    __shared__ float Ks[KCHUNK * DK];
    __shared__ float Vs[KCHUNK * DK];
    __shared__ int   Rs[KV];

    const int blk = blockIdx.x;
    const int h = blk % NHh;
    const int p = (blk / NHh) % Pp;
    const int b = blk / (NHh * Pp);
    const int tid = threadIdx.x;

    if (tid < KV) Rs[tid] = R[(b * Pp + p) * KV + tid];

    const bool active = (tid < LBLK);
    unsigned long long qv2[DK / 2], acc2[DK / 2];
    float m = -1e30f, l = 0.f;
    if (active) {
        const float* qrow = q2 + ((long)((b * Pp + p) * LBLK + tid)) * Cc + h * DK;
#pragma unroll
        for (int d2 = 0; d2 < DK / 2; d2++) {
            qv2[d2] = pk2(qrow[2 * d2] * QK_SCALE, qrow[2 * d2 + 1] * QK_SCALE);
            acc2[d2] = 0ull;
        }
    }

    for (int ch = 0; ch < LKEY / KCHUNK; ch++) {
        __syncthreads();
        const int kg0 = ch * KCHUNK;
        for (int i = tid; i < KCHUNK * (DK / 4); i += blockDim.x) {
            const int row = i >> 3;
            const int d4  = (i & 7) * 4;
            const int kg  = kg0 + row;
            const int ks  = kg / LBLK;
            const int rr  = kg - ks * LBLK;
            const int r   = Rs[ks];
            const long base = ((long)(b * Pp + r) * LBLK + rr) * Cc + h * DK + d4;
            *(float4*)&Ks[row * DK + d4] = *(const float4*)&k2[base];
            *(float4*)&Vs[row * DK + d4] = *(const float4*)&v2[base];
        }
        __syncthreads();
        if (active) {
            for (int k = 0; k < KCHUNK; k++) {
                const unsigned long long* kr = (const unsigned long long*)&Ks[k * DK];
                unsigned long long s0 = 0ull, s1 = 0ull, s2 = 0ull, s3 = 0ull;
#pragma unroll
                for (int d2 = 0; d2 < DK / 2; d2 += 4) {
                    s0 = ffma2(qv2[d2 + 0], kr[d2 + 0], s0);
                    s1 = ffma2(qv2[d2 + 1], kr[d2 + 1], s1);
                    s2 = ffma2(qv2[d2 + 2], kr[d2 + 2], s2);
                    s3 = ffma2(qv2[d2 + 3], kr[d2 + 3], s3);
                }
                const float2 f0 = upk2(s0), f1 = upk2(s1), f2 = upk2(s2), f3 = upk2(s3);
                const float s = ((f0.x + f0.y) + (f1.x + f1.y)) + ((f2.x + f2.y) + (f3.x + f3.y));
                const float mnew = fmaxf(m, s);
                const float corr = fast_exp2(m - mnew);
                const float pe   = fast_exp2(s - mnew);
                l = fmaf(l, corr, pe);
                const unsigned long long cc = pk2(corr, corr);
                const unsigned long long pp = pk2(pe, pe);
                const unsigned long long* vr = (const unsigned long long*)&Vs[k * DK];
#pragma unroll
                for (int d2 = 0; d2 < DK / 2; d2++)
                    acc2[d2] = ffma2(acc2[d2], cc, fmul2(pp, vr[d2]));
                m = mnew;
            }
        }
    }

    if (active) {
        const float inv = 1.0f / l;
        float* orow = ctx + ((long)((b * Pp + p) * LBLK + tid)) * Cc + h * DK;
#pragma unroll
        for (int d2 = 0; d2 < DK / 2; d2++) {
            float2 f = upk2(acc2[d2]);
            orow[2 * d2]     = f.x * inv;
            orow[2 * d2 + 1] = f.y * inv;
        }
    }
}

// ---------------- fused residual add + LayerNorm ----------------
__global__ void add_ln_kernel(const float* __restrict__ a, const float* __restrict__ bsrc,
                              const float* __restrict__ g, const float* __restrict__ beta,
                              float* __restrict__ out)
{
    const int mrow = blockIdx.x;
    const int c = threadIdx.x;
    __shared__ float red[Cc];
    const float v = a[(long)mrow * Cc + c] + bsrc[(long)mrow * Cc + c];
    red[c] = v;
    __syncthreads();
    for (int s = Cc / 2; s > 0; s >>= 1) {
        if (c < s) red[c] += red[c + s];
        __syncthreads();
    }
    const float mean = red[0] * (1.f / (float)Cc);
    __syncthreads();
    const float d = v - mean;
    red[c] = d * d;
    __syncthreads();
    for (int s = Cc / 2; s > 0; s >>= 1) {
        if (c < s) red[c] += red[c + s];
        __syncthreads();
    }
    const float var = red[0] * (1.f / (float)Cc);
    out[(long)mrow * Cc + c] = d * rsqrtf(var + 1e-5f) * g[c] + beta[c];
}

// xres + (sum of NSPLIT conv partials + conv bias) -> LN -> out
__global__ void add_lnK_kernel(const float* __restrict__ a, const float* __restrict__ pbase,
                               const float* __restrict__ cb,
                               const float* __restrict__ g, const float* __restrict__ beta,
                               float* __restrict__ out)
{
    const int mrow = blockIdx.x;
    const int c = threadIdx.x;
    __shared__ float red[Cc];
    const long off = (long)mrow * Cc + c;
    float v = a[off] + cb[c];
#pragma unroll
    for (int s = 0; s < NSPLIT; s++) v += pbase[off + (size_t)s * NELEM];
    red[c] = v;
    __syncthreads();
    for (int s = Cc / 2; s > 0; s >>= 1) {
        if (c < s) red[c] += red[c + s];
        __syncthreads();
    }
    const float mean = red[0] * (1.f / (float)Cc);
    __syncthreads();
    const float d = v - mean;
    red[c] = d * d;
    __syncthreads();
    for (int s = Cc / 2; s > 0; s >>= 1) {
        if (c < s) red[c] += red[c + s];
        __syncthreads();
    }
    const float var = red[0] * (1.f / (float)Cc);
    out[off] = d * rsqrtf(var + 1e-5f) * g[c] + beta[c];
}

// ---------------- launcher ----------------
extern "C" void kernel_launch(void* const* d_in, const int* in_sizes, int n_in,
                              void* d_out, int out_size)
{
    const float* x        = (const float*)d_in[0];
    const float* wq_proj  = (const float*)d_in[1];
    const float* bq_proj  = (const float*)d_in[2];
    const float* wk_proj  = (const float*)d_in[3];
    const float* bk_proj  = (const float*)d_in[4];
    const float* wv_proj  = (const float*)d_in[5];
    const float* bv_proj  = (const float*)d_in[6];
    const float* wq_a     = (const float*)d_in[7];
    const float* bq_a     = (const float*)d_in[8];
    const float* wk_a     = (const float*)d_in[9];
    const float* bk_a     = (const float*)d_in[10];
    const float* wv_a     = (const float*)d_in[11];
    const float* bv_a     = (const float*)d_in[12];
    const float* wo_a     = (const float*)d_in[13];
    const float* bo_a     = (const float*)d_in[14];
    const float* conv_w   = (const float*)d_in[15];
    const float* conv_b   = (const float*)d_in[16];
    const float* ln1_g    = (const float*)d_in[17];
    const float* ln1_b    = (const float*)d_in[18];
    const float* ln2_g    = (const float*)d_in[19];
    const float* ln2_b    = (const float*)d_in[20];
    float* out = (float*)d_out;

    float* buf = nullptr;       cudaGetSymbolAddress((void**)&buf, g_buf);
    float* loc = nullptr;       cudaGetSymbolAddress((void**)&loc, g_loc);
    int*   Rp  = nullptr;       cudaGetSymbolAddress((void**)&Rp, g_R);
    __nv_bfloat16 *kvh = nullptr, *kvl = nullptr, *wth = nullptr, *wtl = nullptr;
    cudaGetSymbolAddress((void**)&kvh, g_kvg_hi);
    cudaGetSymbolAddress((void**)&kvl, g_kvg_lo);
    cudaGetSymbolAddress((void**)&wth, g_wt_hi);
    cudaGetSymbolAddress((void**)&wtl, g_wt_lo);

    float* qp   = buf + 0l  * NELEM;
    float* kp   = buf + 1l  * NELEM;
    float* vp   = buf + 2l  * NELEM;
    float* xres = buf + 3l  * NELEM;
    float* q2   = buf + 4l  * NELEM;
    float* k2   = buf + 5l  * NELEM;
    float* v2   = buf + 6l  * NELEM;
    float* ctx  = buf + 7l  * NELEM;
    float* rout = buf + 8l  * NELEM;
    float* cnvp = buf + 9l  * NELEM;   // NSPLIT partials
    float* qloc = loc;
    float* kloc = loc + 16 * Cc;

    const dim3 gblk(256);

    // 1: fused q/k/v block projections
    {
        GemmSet gs;
        gs.A[0] = x;        gs.A[1] = x;        gs.A[2] = x;
        gs.B[0] = wq_proj;  gs.B[1] = wk_proj;  gs.B[2] = wv_proj;
        gs.bias[0] = bq_proj; gs.bias[1] = bk_proj; gs.bias[2] = bv_proj;
        gs.C[0] = qp;       gs.C[1] = kp;       gs.C[2] = vp;
        gemm3_kernel<<<dim3(NROW / BM, Cc / BN, 3), gblk>>>(gs);
    }

    // 2: weight transpose+decompose (independent of #1)
    decomp_wt_kernel<<<dim3(KTOT / 32, Cc / 32), dim3(32, 8)>>>(conv_w, wth, wtl);

    // 3: conv input decompose (k_p + v_p)
    decomp_kvg_kernel<<<NELEM / 256, 256>>>(kp, vp, kvh, kvl);

    // 4: conv via mma.sync (profiled slot)
    conv_mma_kernel<<<dim3(NROW / 64, Cc / 128, NSPLIT), gblk>>>(kvh, kvl, wth, wtl, cnvp);

    // 5-6: routing
    pool_kernel<<<Bsz * Pp, Cc>>>(qp, kp, qloc, kloc);
    route_kernel<<<Bsz * Pp, 256>>>(qloc, kloc, Rp);

    // 7: fused attention head projections
    {
        GemmSet gs;
        gs.A[0] = qp;       gs.A[1] = kp;       gs.A[2] = vp;
        gs.B[0] = wq_a;     gs.B[1] = wk_a;     gs.B[2] = wv_a;
        gs.bias[0] = bq_a;  gs.bias[1] = bk_a;  gs.bias[2] = bv_a;
        gs.C[0] = q2;       gs.C[1] = k2;       gs.C[2] = v2;
        gemm3_kernel<<<dim3(NROW / BM, Cc / BN, 3), gblk>>>(gs);
    }

    // 8: routed attention
    attention_kernel<<<Bsz * Pp * NHh, 256>>>(q2, k2, v2, Rp, ctx);

    // 9: output projection
    {
        GemmSet gs;
        gs.A[0] = ctx;   gs.A[1] = ctx;   gs.A[2] = ctx;
        gs.B[0] = wo_a;  gs.B[1] = wo_a;  gs.B[2] = wo_a;
        gs.bias[0] = bo_a; gs.bias[1] = bo_a; gs.bias[2] = bo_a;
        gs.C[0] = rout;  gs.C[1] = rout;  gs.C[2] = rout;
        gemm3_kernel<<<dim3(NROW / BM, Cc / BN, 1), gblk>>>(gs);
    }

    // 10-11: LayerNorms
    add_ln_kernel<<<NROW, Cc>>>(x, rout, ln1_g, ln1_b, xres);
    add_lnK_kernel<<<NROW, Cc>>>(xres, cnvp, conv_b, ln2_g, ln2_b, out);
}

// round 5
// speedup vs baseline: 2.2650x; 1.2070x over previous
#include <cuda_runtime.h>
#include <cuda_bf16.h>
#include <math.h>
#include <stdint.h>

// Problem constants
#define Bsz 2
#define Hh  64
#define Ww  24
#define Cc  256
#define Pp  8
#define HP  8
#define NHh 8
#define DK  32
#define KV  4
#define NROW (Bsz*Hh*Ww)       // 3072
#define NELEM (NROW*Cc)        // 786432
#define LBLK (HP*Ww)           // 192
#define LKEY (KV*LBLK)         // 768
#define KTOT (25*Cc)           // 6400 conv K
#define NSPLIT 3               // conv split-K (uneven chunk ranges)
#define NCHUNK 200             // 6400 / 32

#define QK_SCALE (0.17677669529663687f * 1.44269504088896340f)

// ---------------- device scratch ----------------
// slots: 0:qp 1:kp 2:vp 3:xres 4:q2 5:k2 6:v2 7:ctx 8:rout 9..11: conv partials
__device__ float g_buf[12u * NELEM];
__device__ float g_loc[2 * 16 * Cc];
__device__ int   g_R[Bsz * Pp * KV];
__device__ __nv_bfloat16 g_kvg_hi[NELEM];
__device__ __nv_bfloat16 g_kvg_lo[NELEM];
__device__ __nv_bfloat16 g_wt_hi[Cc * KTOT];
__device__ __nv_bfloat16 g_wt_lo[Cc * KTOT];

// ---------------- packed f32x2 helpers ----------------
__device__ __forceinline__ unsigned long long pk2(float lo, float hi) {
    unsigned long long r;
    asm("mov.b64 %0, {%1, %2};" : "=l"(r)
        : "r"(__float_as_uint(lo)), "r"(__float_as_uint(hi)));
    return r;
}
__device__ __forceinline__ unsigned long long ffma2(unsigned long long a,
                                                    unsigned long long b,
                                                    unsigned long long c) {
    unsigned long long d;
    asm("fma.rn.f32x2 %0, %1, %2, %3;" : "=l"(d) : "l"(a), "l"(b), "l"(c));
    return d;
}
__device__ __forceinline__ unsigned long long fmul2(unsigned long long a,
                                                    unsigned long long b) {
    unsigned long long d;
    asm("mul.rn.f32x2 %0, %1, %2;" : "=l"(d) : "l"(a), "l"(b));
    return d;
}
__device__ __forceinline__ float2 upk2(unsigned long long v) {
    unsigned int lo, hi;
    asm("mov.b64 {%0, %1}, %2;" : "=r"(lo), "=r"(hi) : "l"(v));
    return make_float2(__uint_as_float(lo), __uint_as_float(hi));
}

// ---------------- fast exp2 on FMA pipe ----------------
__device__ __forceinline__ float fast_exp2(float x) {
    x = fmaxf(x, -126.0f);
    float fl = floorf(x);
    float f  = x - fl;
    float p  = 1.5403530393381609e-4f;
    p = fmaf(p, f, 1.3333558146428443e-3f);
    p = fmaf(p, f, 9.6181291076284772e-3f);
    p = fmaf(p, f, 5.5504108664821580e-2f);
    p = fmaf(p, f, 2.4022650695910072e-1f);
    p = fmaf(p, f, 6.9314718055994531e-1f);
    p = fmaf(p, f, 1.0f);
    return __int_as_float(__float_as_int(p) + ((int)fl << 23));
}

// ---------------- warp MMA helpers ----------------
__device__ __forceinline__ uint32_t smem_u32(const void* p) {
    uint32_t a;
    asm("{ .reg .u64 t; cvta.to.shared.u64 t, %1; cvt.u32.u64 %0, t; }"
        : "=r"(a) : "l"(p));
    return a;
}
#define SWZ64(o) ((o) ^ (((o) >> 3) & 0x30))

__device__ __forceinline__ void ldsm4(uint32_t* r, uint32_t addr) {
    asm volatile("ldmatrix.sync.aligned.m8n8.x4.shared.b16 {%0,%1,%2,%3}, [%4];"
                 : "=r"(r[0]), "=r"(r[1]), "=r"(r[2]), "=r"(r[3]) : "r"(addr));
}
__device__ __forceinline__ void mma_bf16(float* c, const uint32_t* a, const uint32_t* b) {
    asm volatile(
        "mma.sync.aligned.m16n8k16.row.col.f32.bf16.bf16.f32 "
        "{%0,%1,%2,%3}, {%4,%5,%6,%7}, {%8,%9}, {%0,%1,%2,%3};"
        : "+f"(c[0]), "+f"(c[1]), "+f"(c[2]), "+f"(c[3])
        : "r"(a[0]), "r"(a[1]), "r"(a[2]), "r"(a[3]), "r"(b[0]), "r"(b[1]));
}

// ---------------- conv via mma.sync bf16 hi/lo split, register-pipelined ----------------
// grid (24, 2, 3), 256 threads (8 warps). CTA tile M=128, N=128, K-chunk 32.
// static smem 32KB: A_hi[128][64B] A_lo B_hi[128][64B] B_lo, SW64 rows.
__global__ __launch_bounds__(256, 1)
void conv_mma_kernel(const __nv_bfloat16* __restrict__ a_hi,
                     const __nv_bfloat16* __restrict__ a_lo,
                     const __nv_bfloat16* __restrict__ b_hi,
                     const __nv_bfloat16* __restrict__ b_lo,
                     float* __restrict__ part)
{
    __shared__ char smem[32768];
    const uint32_t sb = smem_u32(smem);
    const uint32_t A_HI = sb, A_LO = sb + 8192, B_HI = sb + 16384, B_LO = sb + 24576;

    const int tid  = threadIdx.x;
    const int wid  = tid >> 5;
    const int lane = tid & 31;
    const int m0 = blockIdx.x * 128;
    const int n0 = blockIdx.y * 128;
    const int z  = blockIdx.z;
    const int cbeg = (z * NCHUNK) / 3;
    const int cend = ((z + 1) * NCHUNK) / 3;

    const int wm = wid & 3;        // 4 m-tiles of 32
    const int wn = wid >> 2;       // 2 n-tiles of 64

    // loader geometry: 2 tasks/thread for A (128 rows x 4 segs) and B
    int a_row[2], a_seg[2], a_h[2], a_w[2];
    long a_base[2];
    int b_rw[2], b_sg[2];
#pragma unroll
    for (int i = 0; i < 2; i++) {
        const int idx = tid + 256 * i;
        a_row[i] = idx >> 2;
        a_seg[i] = idx & 3;
        const int m = m0 + a_row[i];
        const int b = m / (Hh * Ww);
        a_h[i] = (m / Ww) % Hh;
        a_w[i] = m % Ww;
        a_base[i] = (long)b * Hh * Ww * Cc;
        b_rw[i] = idx >> 2;
        b_sg[i] = idx & 3;
    }

    float acc[2][8][4];
#pragma unroll
    for (int i = 0; i < 2; i++)
#pragma unroll
        for (int j = 0; j < 8; j++)
#pragma unroll
            for (int q = 0; q < 4; q++) acc[i][j][q] = 0.f;

    uint4 rAh[2], rAl[2], rBh[2], rBl[2];

    // prefetch first chunk into registers
    {
        const int kb = cbeg * 32;
        const int patch = kb >> 8;
        const int kh = patch / 5, kw = patch % 5;
        const int ci0 = kb & 255;
#pragma unroll
        for (int i = 0; i < 2; i++) {
            const int hh = a_h[i] + kh - 2;
            const int ww = a_w[i] + kw - 2;
            if (hh >= 0 && hh < Hh && ww >= 0 && ww < Ww) {
                const long off = a_base[i] + ((long)hh * Ww + ww) * Cc + ci0 + a_seg[i] * 8;
                rAh[i] = *(const uint4*)(a_hi + off);
                rAl[i] = *(const uint4*)(a_lo + off);
            } else {
                rAh[i] = make_uint4(0, 0, 0, 0);
                rAl[i] = make_uint4(0, 0, 0, 0);
            }
            const long boff = (long)(n0 + b_rw[i]) * KTOT + kb + b_sg[i] * 8;
            rBh[i] = *(const uint4*)(b_hi + boff);
            rBl[i] = *(const uint4*)(b_lo + boff);
        }
    }

    for (int c = cbeg; c < cend; c++) {
        __syncthreads();   // previous chunk's compute done reading smem
        // store current chunk from registers
#pragma unroll
        for (int i = 0; i < 2; i++) {
            const uint32_t soA = SWZ64((uint32_t)(a_row[i] * 64 + a_seg[i] * 16));
            *(uint4*)(smem + soA)        = rAh[i];
            *(uint4*)(smem + 8192 + soA) = rAl[i];
            const uint32_t soB = SWZ64((uint32_t)(b_rw[i] * 64 + b_sg[i] * 16));
            *(uint4*)(smem + 16384 + soB) = rBh[i];
            *(uint4*)(smem + 24576 + soB) = rBl[i];
        }
        __syncthreads();

        // prefetch next chunk (overlaps with MMA below)
        if (c + 1 < cend) {
            const int kb = (c + 1) * 32;
            const int patch = kb >> 8;
            const int kh = patch / 5, kw = patch % 5;
            const int ci0 = kb & 255;
#pragma unroll
            for (int i = 0; i < 2; i++) {
                const int hh = a_h[i] + kh - 2;
                const int ww = a_w[i] + kw - 2;
                if (hh >= 0 && hh < Hh && ww >= 0 && ww < Ww) {
                    const long off = a_base[i] + ((long)hh * Ww + ww) * Cc + ci0 + a_seg[i] * 8;
                    rAh[i] = *(const uint4*)(a_hi + off);
                    rAl[i] = *(const uint4*)(a_lo + off);
                } else {
                    rAh[i] = make_uint4(0, 0, 0, 0);
                    rAl[i] = make_uint4(0, 0, 0, 0);
                }
                const long boff = (long)(n0 + b_rw[i]) * KTOT + kb + b_sg[i] * 8;
                rBh[i] = *(const uint4*)(b_hi + boff);
                rBl[i] = *(const uint4*)(b_lo + boff);
            }
        }

        // compute chunk c: 2 ksteps of k16
#pragma unroll
        for (int kst = 0; kst < 2; kst++) {
            uint32_t ahi[2][4], alo[2][4];
#pragma unroll
            for (int mh = 0; mh < 2; mh++) {
                const int tile = lane >> 3;
                const int row = wm * 32 + mh * 16 + ((tile & 1) << 3) + (lane & 7);
                const int unit = kst * 2 + (tile >> 1);
                const uint32_t so = SWZ64((uint32_t)(row * 64 + unit * 16));
                ldsm4(ahi[mh], A_HI + so);
                ldsm4(alo[mh], A_LO + so);
            }
            uint32_t bhi[8][2], blo[8][2];
#pragma unroll
            for (int ng = 0; ng < 4; ng++) {
                const int tile = lane >> 3;
                const int row = wn * 64 + ng * 16 + ((tile >> 1) << 3) + (lane & 7);
                const int unit = kst * 2 + (tile & 1);
                const uint32_t so = SWZ64((uint32_t)(row * 64 + unit * 16));
                uint32_t th[4], tl[4];
                ldsm4(th, B_HI + so);
                ldsm4(tl, B_LO + so);
                bhi[ng * 2][0] = th[0]; bhi[ng * 2][1] = th[1];
                bhi[ng * 2 + 1][0] = th[2]; bhi[ng * 2 + 1][1] = th[3];
                blo[ng * 2][0] = tl[0]; blo[ng * 2][1] = tl[1];
                blo[ng * 2 + 1][0] = tl[2]; blo[ng * 2 + 1][1] = tl[3];
            }
#pragma unroll
            for (int mh = 0; mh < 2; mh++)
#pragma unroll
                for (int nt = 0; nt < 8; nt++) {
                    mma_bf16(acc[mh][nt], ahi[mh], bhi[nt]);
                    mma_bf16(acc[mh][nt], alo[mh], bhi[nt]);
                    mma_bf16(acc[mh][nt], ahi[mh], blo[nt]);
                }
        }
    }

    // epilogue: write fp32 partials
    float* base = part + (size_t)z * NELEM;
#pragma unroll
    for (int mh = 0; mh < 2; mh++) {
        const int mrow = m0 + wm * 32 + mh * 16 + (lane >> 2);
#pragma unroll
        for (int nt = 0; nt < 8; nt++) {
            const int n = n0 + wn * 64 + nt * 8 + (lane & 3) * 2;
            *(float2*)&base[(size_t)mrow * Cc + n] =
                make_float2(acc[mh][nt][0], acc[mh][nt][1]);
            *(float2*)&base[(size_t)(mrow + 8) * Cc + n] =
                make_float2(acc[mh][nt][2], acc[mh][nt][3]);
        }
    }
}

// ---------------- decompose kvg = kp+vp into bf16 hi/lo ----------------
__global__ void decomp_kvg_kernel(const float* __restrict__ kp, const float* __restrict__ vp,
                                  __nv_bfloat16* __restrict__ hi, __nv_bfloat16* __restrict__ lo)
{
    const int i = blockIdx.x * blockDim.x + threadIdx.x;
    if (i < NELEM) {
        const float v = kp[i] + vp[i];
        const __nv_bfloat16 h = __float2bfloat16(v);
        hi[i] = h;
        lo[i] = __float2bfloat16(v - __bfloat162float(h));
    }
}

// ---------------- transpose + decompose conv weights: [6400,256] -> [256,6400] ----------------
__global__ void decomp_wt_kernel(const float* __restrict__ w,
                                 __nv_bfloat16* __restrict__ hi, __nv_bfloat16* __restrict__ lo)
{
    __shared__ float tile[32][33];
    const int k0 = blockIdx.x * 32;
    const int n0 = blockIdx.y * 32;
    const int tx = threadIdx.x, ty = threadIdx.y;   // 32 x 8
#pragma unroll
    for (int i = 0; i < 4; i++)
        tile[ty + i * 8][tx] = w[(long)(k0 + ty + i * 8) * Cc + n0 + tx];
    __syncthreads();
#pragma unroll
    for (int i = 0; i < 4; i++) {
        const float v = tile[tx][ty + i * 8];
        const __nv_bfloat16 h = __float2bfloat16(v);
        const long o = (long)(n0 + ty + i * 8) * KTOT + k0 + tx;
        hi[o] = h;
        lo[o] = __float2bfloat16(v - __bfloat162float(h));
    }
}

// ---------------- fused triple GEMM (FFMA2 SIMT) ----------------
#define BM 64
#define BN 64
#define BK 16

struct GemmSet {
    const float* A[3];
    const float* B[3];
    const float* bias[3];
    float*       C[3];
};

__global__ void gemm3_kernel(GemmSet gs)
{
    __shared__ float As[BK][BM];
    __shared__ float Bs[BK][BN];
    const int zz = blockIdx.z;
    const float* __restrict__ A    = gs.A[zz];
    const float* __restrict__ Bm   = gs.B[zz];
    const float* __restrict__ bias = gs.bias[zz];
    float* __restrict__ C          = gs.C[zz];

    const int tid = threadIdx.x;
    const int m0 = blockIdx.x * BM;
    const int n0 = blockIdx.y * BN;
    const int ty = tid >> 4;
    const int tx = tid & 15;
    const int a_mm = tid >> 2;
    const int a_kk = (tid & 3) * 4;
    const int b_kk = tid >> 4;
    const int b_nn = (tid & 15) * 4;

    unsigned long long acc2[4][2];
#pragma unroll
    for (int i = 0; i < 4; i++) { acc2[i][0] = 0ull; acc2[i][1] = 0ull; }

    for (int k0 = 0; k0 < Cc; k0 += BK) {
        float4 av = *(const float4*)&A[(long)(m0 + a_mm) * Cc + k0 + a_kk];
        As[a_kk + 0][a_mm] = av.x;
        As[a_kk + 1][a_mm] = av.y;
        As[a_kk + 2][a_mm] = av.z;
        As[a_kk + 3][a_mm] = av.w;
        *(float4*)&Bs[b_kk][b_nn] = *(const float4*)&Bm[(long)(k0 + b_kk) * Cc + n0 + b_nn];
        __syncthreads();
#pragma unroll
        for (int kk = 0; kk < BK; kk++) {
            const float4 a4 = *(const float4*)&As[kk][ty * 4];
            const ulonglong2 b2 = *(const ulonglong2*)&Bs[kk][tx * 4];
            unsigned long long p0 = pk2(a4.x, a4.x);
            unsigned long long p1 = pk2(a4.y, a4.y);
            unsigned long long p2 = pk2(a4.z, a4.z);
            unsigned long long p3 = pk2(a4.w, a4.w);
            acc2[0][0] = ffma2(p0, b2.x, acc2[0][0]);
            acc2[0][1] = ffma2(p0, b2.y, acc2[0][1]);
            acc2[1][0] = ffma2(p1, b2.x, acc2[1][0]);
            acc2[1][1] = ffma2(p1, b2.y, acc2[1][1]);
            acc2[2][0] = ffma2(p2, b2.x, acc2[2][0]);
            acc2[2][1] = ffma2(p2, b2.y, acc2[2][1]);
            acc2[3][0] = ffma2(p3, b2.x, acc2[3][0]);
            acc2[3][1] = ffma2(p3, b2.y, acc2[3][1]);
        }
        __syncthreads();
    }

    const float4 bi = *(const float4*)&bias[n0 + tx * 4];
#pragma unroll
    for (int i = 0; i < 4; i++) {
        const long row = m0 + ty * 4 + i;
        float2 f0 = upk2(acc2[i][0]);
        float2 f1 = upk2(acc2[i][1]);
        *(float4*)&C[row * Cc + n0 + tx * 4] =
            make_float4(f0.x + bi.x, f0.y + bi.y, f1.x + bi.z, f1.y + bi.w);
    }
}

// ---------------- block mean pooling ----------------
__global__ void pool_kernel(const float* __restrict__ qp, const float* __restrict__ kp,
                            float* __restrict__ qloc, float* __restrict__ kloc)
{
    const int bp = blockIdx.x;
    const int c  = threadIdx.x;
    const float* qb = qp + (long)bp * LBLK * Cc + c;
    const float* kb = kp + (long)bp * LBLK * Cc + c;
    float sq = 0.f, sk = 0.f;
    for (int i = 0; i < LBLK; i++) { sq += qb[i * Cc]; sk += kb[i * Cc]; }
    qloc[bp * Cc + c] = sq * (1.f / (float)LBLK);
    kloc[bp * Cc + c] = sk * (1.f / (float)LBLK);
}

// ---------------- routing ----------------
__global__ void route_kernel(const float* __restrict__ qloc, const float* __restrict__ kloc,
                             int* __restrict__ R)
{
    const int bp = blockIdx.x;
    const int b  = bp / Pp;
    const int warp = threadIdx.x >> 5;
    const int lane = threadIdx.x & 31;
    __shared__ float s[8];
    const float* q = qloc + bp * Cc;
    const float* k = kloc + (b * Pp + warp) * Cc;
    float partial = 0.f;
    for (int c = lane; c < Cc; c += 32) partial += q[c] * k[c];
#pragma unroll
    for (int o = 16; o; o >>= 1) partial += __shfl_xor_sync(0xffffffff, partial, o);
    if (lane == 0) s[warp] = partial;
    __syncthreads();
    if (threadIdx.x == 0) {
        bool used[8] = {};
        for (int t = 0; t < KV; t++) {
            int best = 0; float bv = -1e30f;
            for (int j = 0; j < Pp; j++)
                if (!used[j] && s[j] > bv) { bv = s[j]; best = j; }
            used[best] = true;
            R[bp * KV + t] = best;
        }
    }
}

// ---------------- attention ----------------
#define KCHUNK 128
__global__ void attention_kernel(const float* __restrict__ q2,
                                 const float* __restrict__ k2,
                                 const float* __restrict__ v2,
                                 const int* __restrict__ R,
                                 float* __restrict__ ctx)
{
    __shared__ float Ks[KCHUNK * DK];
    __shared__ float Vs[KCHUNK * DK];
    __shared__ int   Rs[KV];

    const int blk = blockIdx.x;
    const int h = blk % NHh;
    const int p = (blk / NHh) % Pp;
    const int b = blk / (NHh * Pp);
    const int tid = threadIdx.x;

    if (tid < KV) Rs[tid] = R[(b * Pp + p) * KV + tid];

    const bool active = (tid < LBLK);
    unsigned long long qv2[DK / 2], acc2[DK / 2];
    float m = -1e30f, l = 0.f;
    if (active) {
        const float* qrow = q2 + ((long)((b * Pp + p) * LBLK + tid)) * Cc + h * DK;
#pragma unroll
        for (int d2 = 0; d2 < DK / 2; d2++) {
            qv2[d2] = pk2(qrow[2 * d2] * QK_SCALE, qrow[2 * d2 + 1] * QK_SCALE);
            acc2[d2] = 0ull;
        }
    }

    for (int ch = 0; ch < LKEY / KCHUNK; ch++) {
        __syncthreads();
        const int kg0 = ch * KCHUNK;
        for (int i = tid; i < KCHUNK * (DK / 4); i += blockDim.x) {
            const int row = i >> 3;
            const int d4  = (i & 7) * 4;
            const int kg  = kg0 + row;
            const int ks  = kg / LBLK;
            const int rr  = kg - ks * LBLK;
            const int r   = Rs[ks];
            const long base = ((long)(b * Pp + r) * LBLK + rr) * Cc + h * DK + d4;
            *(float4*)&Ks[row * DK + d4] = *(const float4*)&k2[base];
            *(float4*)&Vs[row * DK + d4] = *(const float4*)&v2[base];
        }
        __syncthreads();
        if (active) {
            for (int k = 0; k < KCHUNK; k++) {
                const unsigned long long* kr = (const unsigned long long*)&Ks[k * DK];
                unsigned long long s0 = 0ull, s1 = 0ull, s2 = 0ull, s3 = 0ull;
#pragma unroll
                for (int d2 = 0; d2 < DK / 2; d2 += 4) {
                    s0 = ffma2(qv2[d2 + 0], kr[d2 + 0], s0);
                    s1 = ffma2(qv2[d2 + 1], kr[d2 + 1], s1);
                    s2 = ffma2(qv2[d2 + 2], kr[d2 + 2], s2);
                    s3 = ffma2(qv2[d2 + 3], kr[d2 + 3], s3);
                }
                const float2 f0 = upk2(s0), f1 = upk2(s1), f2 = upk2(s2), f3 = upk2(s3);
                const float s = ((f0.x + f0.y) + (f1.x + f1.y)) + ((f2.x + f2.y) + (f3.x + f3.y));
                const float mnew = fmaxf(m, s);
                const float corr = fast_exp2(m - mnew);
                const float pe   = fast_exp2(s - mnew);
                l = fmaf(l, corr, pe);
                const unsigned long long cc = pk2(corr, corr);
                const unsigned long long pp = pk2(pe, pe);
                const unsigned long long* vr = (const unsigned long long*)&Vs[k * DK];
#pragma unroll
                for (int d2 = 0; d2 < DK / 2; d2++)
                    acc2[d2] = ffma2(acc2[d2], cc, fmul2(pp, vr[d2]));
                m = mnew;
            }
        }
    }

    if (active) {
        const float inv = 1.0f / l;
        float* orow = ctx + ((long)((b * Pp + p) * LBLK + tid)) * Cc + h * DK;
#pragma unroll
        for (int d2 = 0; d2 < DK / 2; d2++) {
            float2 f = upk2(acc2[d2]);
            orow[2 * d2]     = f.x * inv;
            orow[2 * d2 + 1] = f.y * inv;
        }
    }
}

// ---------------- fused residual add + LayerNorm ----------------
__global__ void add_ln_kernel(const float* __restrict__ a, const float* __restrict__ bsrc,
                              const float* __restrict__ g, const float* __restrict__ beta,
                              float* __restrict__ out)
{
    const int mrow = blockIdx.x;
    const int c = threadIdx.x;
    __shared__ float red[Cc];
    const float v = a[(long)mrow * Cc + c] + bsrc[(long)mrow * Cc + c];
    red[c] = v;
    __syncthreads();
    for (int s = Cc / 2; s > 0; s >>= 1) {
        if (c < s) red[c] += red[c + s];
        __syncthreads();
    }
    const float mean = red[0] * (1.f / (float)Cc);
    __syncthreads();
    const float d = v - mean;
    red[c] = d * d;
    __syncthreads();
    for (int s = Cc / 2; s > 0; s >>= 1) {
        if (c < s) red[c] += red[c + s];
        __syncthreads();
    }
    const float var = red[0] * (1.f / (float)Cc);
    out[(long)mrow * Cc + c] = d * rsqrtf(var + 1e-5f) * g[c] + beta[c];
}

// xres + (sum of NSPLIT conv partials + conv bias) -> LN -> out
__global__ void add_lnK_kernel(const float* __restrict__ a, const float* __restrict__ pbase,
                               const float* __restrict__ cb,
                               const float* __restrict__ g, const float* __restrict__ beta,
                               float* __restrict__ out)
{
    const int mrow = blockIdx.x;
    const int c = threadIdx.x;
    __shared__ float red[Cc];
    const long off = (long)mrow * Cc + c;
    float v = a[off] + cb[c];
#pragma unroll
    for (int s = 0; s < NSPLIT; s++) v += pbase[off + (size_t)s * NELEM];
    red[c] = v;
    __syncthreads();
    for (int s = Cc / 2; s > 0; s >>= 1) {
        if (c < s) red[c] += red[c + s];
        __syncthreads();
    }
    const float mean = red[0] * (1.f / (float)Cc);
    __syncthreads();
    const float d = v - mean;
    red[c] = d * d;
    __syncthreads();
    for (int s = Cc / 2; s > 0; s >>= 1) {
        if (c < s) red[c] += red[c + s];
        __syncthreads();
    }
    const float var = red[0] * (1.f / (float)Cc);
    out[off] = d * rsqrtf(var + 1e-5f) * g[c] + beta[c];
}

// ---------------- launcher ----------------
extern "C" void kernel_launch(void* const* d_in, const int* in_sizes, int n_in,
                              void* d_out, int out_size)
{
    const float* x        = (const float*)d_in[0];
    const float* wq_proj  = (const float*)d_in[1];
    const float* bq_proj  = (const float*)d_in[2];
    const float* wk_proj  = (const float*)d_in[3];
    const float* bk_proj  = (const float*)d_in[4];
    const float* wv_proj  = (const float*)d_in[5];
    const float* bv_proj  = (const float*)d_in[6];
    const float* wq_a     = (const float*)d_in[7];
    const float* bq_a     = (const float*)d_in[8];
    const float* wk_a     = (const float*)d_in[9];
    const float* bk_a     = (const float*)d_in[10];
    const float* wv_a     = (const float*)d_in[11];
    const float* bv_a     = (const float*)d_in[12];
    const float* wo_a     = (const float*)d_in[13];
    const float* bo_a     = (const float*)d_in[14];
    const float* conv_w   = (const float*)d_in[15];
    const float* conv_b   = (const float*)d_in[16];
    const float* ln1_g    = (const float*)d_in[17];
    const float* ln1_b    = (const float*)d_in[18];
    const float* ln2_g    = (const float*)d_in[19];
    const float* ln2_b    = (const float*)d_in[20];
    float* out = (float*)d_out;

    float* buf = nullptr;       cudaGetSymbolAddress((void**)&buf, g_buf);
    float* loc = nullptr;       cudaGetSymbolAddress((void**)&loc, g_loc);
    int*   Rp  = nullptr;       cudaGetSymbolAddress((void**)&Rp, g_R);
    __nv_bfloat16 *kvh = nullptr, *kvl = nullptr, *wth = nullptr, *wtl = nullptr;
    cudaGetSymbolAddress((void**)&kvh, g_kvg_hi);
    cudaGetSymbolAddress((void**)&kvl, g_kvg_lo);
    cudaGetSymbolAddress((void**)&wth, g_wt_hi);
    cudaGetSymbolAddress((void**)&wtl, g_wt_lo);

    float* qp   = buf + 0l  * NELEM;
    float* kp   = buf + 1l  * NELEM;
    float* vp   = buf + 2l  * NELEM;
    float* xres = buf + 3l  * NELEM;
    float* q2   = buf + 4l  * NELEM;
    float* k2   = buf + 5l  * NELEM;
    float* v2   = buf + 6l  * NELEM;
    float* ctx  = buf + 7l  * NELEM;
    float* rout = buf + 8l  * NELEM;
    float* cnvp = buf + 9l  * NELEM;   // NSPLIT partials
    float* qloc = loc;
    float* kloc = loc + 16 * Cc;

    const dim3 gblk(256);

    // 1: fused q/k/v block projections
    {
        GemmSet gs;
        gs.A[0] = x;        gs.A[1] = x;        gs.A[2] = x;
        gs.B[0] = wq_proj;  gs.B[1] = wk_proj;  gs.B[2] = wv_proj;
        gs.bias[0] = bq_proj; gs.bias[1] = bk_proj; gs.bias[2] = bv_proj;
        gs.C[0] = qp;       gs.C[1] = kp;       gs.C[2] = vp;
        gemm3_kernel<<<dim3(NROW / BM, Cc / BN, 3), gblk>>>(gs);
    }

    // 2: weight transpose+decompose (independent of #1)
    decomp_wt_kernel<<<dim3(KTOT / 32, Cc / 32), dim3(32, 8)>>>(conv_w, wth, wtl);

    // 3: conv input decompose (k_p + v_p)
    decomp_kvg_kernel<<<NELEM / 256, 256>>>(kp, vp, kvh, kvl);

    // 4: conv via pipelined mma.sync (profiled slot)
    conv_mma_kernel<<<dim3(NROW / 128, Cc / 128, NSPLIT), gblk>>>(kvh, kvl, wth, wtl, cnvp);

    // 5-6: routing
    pool_kernel<<<Bsz * Pp, Cc>>>(qp, kp, qloc, kloc);
    route_kernel<<<Bsz * Pp, 256>>>(qloc, kloc, Rp);

    // 7: fused attention head projections
    {
        GemmSet gs;
        gs.A[0] = qp;       gs.A[1] = kp;       gs.A[2] = vp;
        gs.B[0] = wq_a;     gs.B[1] = wk_a;     gs.B[2] = wv_a;
        gs.bias[0] = bq_a;  gs.bias[1] = bk_a;  gs.bias[2] = bv_a;
        gs.C[0] = q2;       gs.C[1] = k2;       gs.C[2] = v2;
        gemm3_kernel<<<dim3(NROW / BM, Cc / BN, 3), gblk>>>(gs);
    }

    // 8: routed attention
    attention_kernel<<<Bsz * Pp * NHh, 256>>>(q2, k2, v2, Rp, ctx);

    // 9: output projection
    {
        GemmSet gs;
        gs.A[0] = ctx;   gs.A[1] = ctx;   gs.A[2] = ctx;
        gs.B[0] = wo_a;  gs.B[1] = wo_a;  gs.B[2] = wo_a;
        gs.bias[0] = bo_a; gs.bias[1] = bo_a; gs.bias[2] = bo_a;
        gs.C[0] = rout;  gs.C[1] = rout;  gs.C[2] = rout;
        gemm3_kernel<<<dim3(NROW / BM, Cc / BN, 1), gblk>>>(gs);
    }

    // 10-11: LayerNorms
    add_ln_kernel<<<NROW, Cc>>>(x, rout, ln1_g, ln1_b, xres);
    add_lnK_kernel<<<NROW, Cc>>>(xres, cnvp, conv_b, ln2_g, ln2_b, out);
}

// round 6
// speedup vs baseline: 2.6337x; 1.1627x over previous
#include <cuda_runtime.h>
#include <cuda_bf16.h>
#include <math.h>
#include <stdint.h>

// Problem constants
#define Bsz 2
#define Hh  64
#define Ww  24
#define Cc  256
#define Pp  8
#define HP  8
#define NHh 8
#define DK  32
#define KV  4
#define NROW (Bsz*Hh*Ww)       // 3072
#define NELEM (NROW*Cc)        // 786432
#define LBLK (HP*Ww)           // 192
#define LKEY (KV*LBLK)         // 768
#define KTOT (25*Cc)           // 6400 conv K
#define NSPLIT 3               // conv split-K
#define NCHUNK 200             // 6400 / 32

#define QK_SCALE (0.17677669529663687f * 1.44269504088896340f)

// ---------------- device scratch ----------------
// fp32 slots: 0:qp 1:kp 2:vp 3:xres 4:q2 5:k2 6:v2 7:rout 8..10:conv partials
__device__ float g_buf[11u * NELEM];
__device__ float g_loc[2 * 16 * Cc];
__device__ int   g_R[Bsz * Pp * KV];
__device__ __nv_bfloat16 g_x_hi[NELEM],   g_x_lo[NELEM];
__device__ __nv_bfloat16 g_act_hi[3u*NELEM], g_act_lo[3u*NELEM];   // qp,kp,vp
__device__ __nv_bfloat16 g_ctx_hi[NELEM], g_ctx_lo[NELEM];
__device__ __nv_bfloat16 g_kvg_hi[NELEM], g_kvg_lo[NELEM];
__device__ __nv_bfloat16 g_wt_hi[Cc * KTOT], g_wt_lo[Cc * KTOT];   // conv W^T
__device__ __nv_bfloat16 g_w7_hi[7u*Cc*Cc], g_w7_lo[7u*Cc*Cc];     // 7 proj W^T

// ---------------- packed f32x2 helpers ----------------
__device__ __forceinline__ unsigned long long pk2(float lo, float hi) {
    unsigned long long r;
    asm("mov.b64 %0, {%1, %2};" : "=l"(r)
        : "r"(__float_as_uint(lo)), "r"(__float_as_uint(hi)));
    return r;
}
__device__ __forceinline__ unsigned long long ffma2(unsigned long long a,
                                                    unsigned long long b,
                                                    unsigned long long c) {
    unsigned long long d;
    asm("fma.rn.f32x2 %0, %1, %2, %3;" : "=l"(d) : "l"(a), "l"(b), "l"(c));
    return d;
}
__device__ __forceinline__ unsigned long long fmul2(unsigned long long a,
                                                    unsigned long long b) {
    unsigned long long d;
    asm("mul.rn.f32x2 %0, %1, %2;" : "=l"(d) : "l"(a), "l"(b));
    return d;
}
__device__ __forceinline__ float2 upk2(unsigned long long v) {
    unsigned int lo, hi;
    asm("mov.b64 {%0, %1}, %2;" : "=r"(lo), "=r"(hi) : "l"(v));
    return make_float2(__uint_as_float(lo), __uint_as_float(hi));
}

// ---------------- fast exp2 on FMA pipe ----------------
__device__ __forceinline__ float fast_exp2(float x) {
    x = fmaxf(x, -126.0f);
    float fl = floorf(x);
    float f  = x - fl;
    float p  = 1.5403530393381609e-4f;
    p = fmaf(p, f, 1.3333558146428443e-3f);
    p = fmaf(p, f, 9.6181291076284772e-3f);
    p = fmaf(p, f, 5.5504108664821580e-2f);
    p = fmaf(p, f, 2.4022650695910072e-1f);
    p = fmaf(p, f, 6.9314718055994531e-1f);
    p = fmaf(p, f, 1.0f);
    return __int_as_float(__float_as_int(p) + ((int)fl << 23));
}

// ---------------- warp MMA helpers ----------------
__device__ __forceinline__ uint32_t smem_u32(const void* p) {
    uint32_t a;
    asm("{ .reg .u64 t; cvta.to.shared.u64 t, %1; cvt.u32.u64 %0, t; }"
        : "=r"(a) : "l"(p));
    return a;
}
#define SWZ64(o) ((o) ^ (((o) >> 3) & 0x30))

__device__ __forceinline__ void ldsm4(uint32_t* r, uint32_t addr) {
    asm volatile("ldmatrix.sync.aligned.m8n8.x4.shared.b16 {%0,%1,%2,%3}, [%4];"
                 : "=r"(r[0]), "=r"(r[1]), "=r"(r[2]), "=r"(r[3]) : "r"(addr));
}
__device__ __forceinline__ void mma_bf16(float* c, const uint32_t* a, const uint32_t* b) {
    asm volatile(
        "mma.sync.aligned.m16n8k16.row.col.f32.bf16.bf16.f32 "
        "{%0,%1,%2,%3}, {%4,%5,%6,%7}, {%8,%9}, {%0,%1,%2,%3};"
        : "+f"(c[0]), "+f"(c[1]), "+f"(c[2]), "+f"(c[3])
        : "r"(a[0]), "r"(a[1]), "r"(a[2]), "r"(a[3]), "r"(b[0]), "r"(b[1]));
}

// ================= tensor-core projection GEMM (hi/lo split) =================
// C[M=3072, N=256] = A[3072,256] @ W[256,256] + bias.  A,B given as bf16 hi/lo.
// CTA tile 128x128, K-chunk 32, register pipelined. grid (24, 2, nz), 256 thr.
struct GemmSetT {
    const __nv_bfloat16 *Ah[3], *Al[3], *Bh[3], *Bl[3];
    const float* bias[3];
    float* C[3];
    __nv_bfloat16 *Ch[3], *Cl[3];   // optional (null => skip)
};

__global__ __launch_bounds__(256, 1)
void gemm_mma_kernel(GemmSetT gs)
{
    __shared__ char smem[32768];
    const uint32_t sb = smem_u32(smem);
    const uint32_t A_HI = sb, A_LO = sb + 8192, B_HI = sb + 16384, B_LO = sb + 24576;

    const int z = blockIdx.z;
    const __nv_bfloat16* __restrict__ Ah = gs.Ah[z];
    const __nv_bfloat16* __restrict__ Al = gs.Al[z];
    const __nv_bfloat16* __restrict__ Bh = gs.Bh[z];
    const __nv_bfloat16* __restrict__ Bl = gs.Bl[z];
    const float* __restrict__ bias = gs.bias[z];
    float* __restrict__ C = gs.C[z];
    __nv_bfloat16* __restrict__ Ch = gs.Ch[z];
    __nv_bfloat16* __restrict__ Cl = gs.Cl[z];

    const int tid  = threadIdx.x;
    const int wid  = tid >> 5;
    const int lane = tid & 31;
    const int m0 = blockIdx.x * 128;
    const int n0 = blockIdx.y * 128;
    const int wm = wid & 3;
    const int wn = wid >> 2;

    int l_row[2], l_seg[2];
#pragma unroll
    for (int i = 0; i < 2; i++) {
        const int idx = tid + 256 * i;
        l_row[i] = idx >> 2;
        l_seg[i] = idx & 3;
    }

    float acc[2][8][4];
#pragma unroll
    for (int i = 0; i < 2; i++)
#pragma unroll
        for (int j = 0; j < 8; j++)
#pragma unroll
            for (int q = 0; q < 4; q++) acc[i][j][q] = 0.f;

    uint4 rAh[2], rAl[2], rBh[2], rBl[2];
#pragma unroll
    for (int i = 0; i < 2; i++) {
        const long aoff = (long)(m0 + l_row[i]) * Cc + l_seg[i] * 8;
        rAh[i] = *(const uint4*)(Ah + aoff);
        rAl[i] = *(const uint4*)(Al + aoff);
        const long boff = (long)(n0 + l_row[i]) * Cc + l_seg[i] * 8;
        rBh[i] = *(const uint4*)(Bh + boff);
        rBl[i] = *(const uint4*)(Bl + boff);
    }

    for (int c = 0; c < 8; c++) {
        __syncthreads();
#pragma unroll
        for (int i = 0; i < 2; i++) {
            const uint32_t so = SWZ64((uint32_t)(l_row[i] * 64 + l_seg[i] * 16));
            *(uint4*)(smem + so)         = rAh[i];
            *(uint4*)(smem + 8192 + so)  = rAl[i];
            *(uint4*)(smem + 16384 + so) = rBh[i];
            *(uint4*)(smem + 24576 + so) = rBl[i];
        }
        __syncthreads();

        if (c + 1 < 8) {
            const int kb = (c + 1) * 32;
#pragma unroll
            for (int i = 0; i < 2; i++) {
                const long aoff = (long)(m0 + l_row[i]) * Cc + kb + l_seg[i] * 8;
                rAh[i] = *(const uint4*)(Ah + aoff);
                rAl[i] = *(const uint4*)(Al + aoff);
                const long boff = (long)(n0 + l_row[i]) * Cc + kb + l_seg[i] * 8;
                rBh[i] = *(const uint4*)(Bh + boff);
                rBl[i] = *(const uint4*)(Bl + boff);
            }
        }

#pragma unroll
        for (int kst = 0; kst < 2; kst++) {
            uint32_t ahi[2][4], alo[2][4];
#pragma unroll
            for (int mh = 0; mh < 2; mh++) {
                const int tile = lane >> 3;
                const int row = wm * 32 + mh * 16 + ((tile & 1) << 3) + (lane & 7);
                const int unit = kst * 2 + (tile >> 1);
                const uint32_t so = SWZ64((uint32_t)(row * 64 + unit * 16));
                ldsm4(ahi[mh], A_HI + so);
                ldsm4(alo[mh], A_LO + so);
            }
            uint32_t bhi[8][2], blo[8][2];
#pragma unroll
            for (int ng = 0; ng < 4; ng++) {
                const int tile = lane >> 3;
                const int row = wn * 64 + ng * 16 + ((tile >> 1) << 3) + (lane & 7);
                const int unit = kst * 2 + (tile & 1);
                const uint32_t so = SWZ64((uint32_t)(row * 64 + unit * 16));
                uint32_t th[4], tl[4];
                ldsm4(th, B_HI + so);
                ldsm4(tl, B_LO + so);
                bhi[ng * 2][0] = th[0]; bhi[ng * 2][1] = th[1];
                bhi[ng * 2 + 1][0] = th[2]; bhi[ng * 2 + 1][1] = th[3];
                blo[ng * 2][0] = tl[0]; blo[ng * 2][1] = tl[1];
                blo[ng * 2 + 1][0] = tl[2]; blo[ng * 2 + 1][1] = tl[3];
            }
#pragma unroll
            for (int mh = 0; mh < 2; mh++)
#pragma unroll
                for (int nt = 0; nt < 8; nt++) {
                    mma_bf16(acc[mh][nt], ahi[mh], bhi[nt]);
                    mma_bf16(acc[mh][nt], alo[mh], bhi[nt]);
                    mma_bf16(acc[mh][nt], ahi[mh], blo[nt]);
                }
        }
    }

    // epilogue: bias + fp32 C + optional bf16 hi/lo decompose
#pragma unroll
    for (int mh = 0; mh < 2; mh++) {
        const int mrow = m0 + wm * 32 + mh * 16 + (lane >> 2);
#pragma unroll
        for (int nt = 0; nt < 8; nt++) {
            const int n = n0 + wn * 64 + nt * 8 + (lane & 3) * 2;
            const float2 bi = *(const float2*)&bias[n];
            const float v0 = acc[mh][nt][0] + bi.x;
            const float v1 = acc[mh][nt][1] + bi.y;
            const float v2 = acc[mh][nt][2] + bi.x;
            const float v3 = acc[mh][nt][3] + bi.y;
            const size_t o0 = (size_t)mrow * Cc + n;
            const size_t o1 = (size_t)(mrow + 8) * Cc + n;
            *(float2*)&C[o0] = make_float2(v0, v1);
            *(float2*)&C[o1] = make_float2(v2, v3);
            if (Ch) {
                const __nv_bfloat16 h0 = __float2bfloat16(v0);
                const __nv_bfloat16 h1 = __float2bfloat16(v1);
                const __nv_bfloat16 h2 = __float2bfloat16(v2);
                const __nv_bfloat16 h3 = __float2bfloat16(v3);
                *(__nv_bfloat162*)&Ch[o0] = __nv_bfloat162(h0, h1);
                *(__nv_bfloat162*)&Ch[o1] = __nv_bfloat162(h2, h3);
                *(__nv_bfloat162*)&Cl[o0] = __nv_bfloat162(
                    __float2bfloat16(v0 - __bfloat162float(h0)),
                    __float2bfloat16(v1 - __bfloat162float(h1)));
                *(__nv_bfloat162*)&Cl[o1] = __nv_bfloat162(
                    __float2bfloat16(v2 - __bfloat162float(h2)),
                    __float2bfloat16(v3 - __bfloat162float(h3)));
            }
        }
    }
}

// ---------------- conv via mma.sync bf16 hi/lo split, register-pipelined ----------------
__global__ __launch_bounds__(256, 1)
void conv_mma_kernel(const __nv_bfloat16* __restrict__ a_hi,
                     const __nv_bfloat16* __restrict__ a_lo,
                     const __nv_bfloat16* __restrict__ b_hi,
                     const __nv_bfloat16* __restrict__ b_lo,
                     float* __restrict__ part)
{
    __shared__ char smem[32768];
    const uint32_t sb = smem_u32(smem);
    const uint32_t A_HI = sb, A_LO = sb + 8192, B_HI = sb + 16384, B_LO = sb + 24576;

    const int tid  = threadIdx.x;
    const int wid  = tid >> 5;
    const int lane = tid & 31;
    const int m0 = blockIdx.x * 128;
    const int n0 = blockIdx.y * 128;
    const int z  = blockIdx.z;
    const int cbeg = (z * NCHUNK) / 3;
    const int cend = ((z + 1) * NCHUNK) / 3;

    const int wm = wid & 3;
    const int wn = wid >> 2;

    int a_row[2], a_seg[2], a_h[2], a_w[2];
    long a_base[2];
    int b_rw[2], b_sg[2];
#pragma unroll
    for (int i = 0; i < 2; i++) {
        const int idx = tid + 256 * i;
        a_row[i] = idx >> 2;
        a_seg[i] = idx & 3;
        const int m = m0 + a_row[i];
        const int b = m / (Hh * Ww);
        a_h[i] = (m / Ww) % Hh;
        a_w[i] = m % Ww;
        a_base[i] = (long)b * Hh * Ww * Cc;
        b_rw[i] = idx >> 2;
        b_sg[i] = idx & 3;
    }

    float acc[2][8][4];
#pragma unroll
    for (int i = 0; i < 2; i++)
#pragma unroll
        for (int j = 0; j < 8; j++)
#pragma unroll
            for (int q = 0; q < 4; q++) acc[i][j][q] = 0.f;

    uint4 rAh[2], rAl[2], rBh[2], rBl[2];
    {
        const int kb = cbeg * 32;
        const int patch = kb >> 8;
        const int kh = patch / 5, kw = patch % 5;
        const int ci0 = kb & 255;
#pragma unroll
        for (int i = 0; i < 2; i++) {
            const int hh = a_h[i] + kh - 2;
            const int ww = a_w[i] + kw - 2;
            if (hh >= 0 && hh < Hh && ww >= 0 && ww < Ww) {
                const long off = a_base[i] + ((long)hh * Ww + ww) * Cc + ci0 + a_seg[i] * 8;
                rAh[i] = *(const uint4*)(a_hi + off);
                rAl[i] = *(const uint4*)(a_lo + off);
            } else {
                rAh[i] = make_uint4(0, 0, 0, 0);
                rAl[i] = make_uint4(0, 0, 0, 0);
            }
            const long boff = (long)(n0 + b_rw[i]) * KTOT + kb + b_sg[i] * 8;
            rBh[i] = *(const uint4*)(b_hi + boff);
            rBl[i] = *(const uint4*)(b_lo + boff);
        }
    }

    for (int c = cbeg; c < cend; c++) {
        __syncthreads();
#pragma unroll
        for (int i = 0; i < 2; i++) {
            const uint32_t soA = SWZ64((uint32_t)(a_row[i] * 64 + a_seg[i] * 16));
            *(uint4*)(smem + soA)        = rAh[i];
            *(uint4*)(smem + 8192 + soA) = rAl[i];
            const uint32_t soB = SWZ64((uint32_t)(b_rw[i] * 64 + b_sg[i] * 16));
            *(uint4*)(smem + 16384 + soB) = rBh[i];
            *(uint4*)(smem + 24576 + soB) = rBl[i];
        }
        __syncthreads();

        if (c + 1 < cend) {
            const int kb = (c + 1) * 32;
            const int patch = kb >> 8;
            const int kh = patch / 5, kw = patch % 5;
            const int ci0 = kb & 255;
#pragma unroll
            for (int i = 0; i < 2; i++) {
                const int hh = a_h[i] + kh - 2;
                const int ww = a_w[i] + kw - 2;
                if (hh >= 0 && hh < Hh && ww >= 0 && ww < Ww) {
                    const long off = a_base[i] + ((long)hh * Ww + ww) * Cc + ci0 + a_seg[i] * 8;
                    rAh[i] = *(const uint4*)(a_hi + off);
                    rAl[i] = *(const uint4*)(a_lo + off);
                } else {
                    rAh[i] = make_uint4(0, 0, 0, 0);
                    rAl[i] = make_uint4(0, 0, 0, 0);
                }
                const long boff = (long)(n0 + b_rw[i]) * KTOT + kb + b_sg[i] * 8;
                rBh[i] = *(const uint4*)(b_hi + boff);
                rBl[i] = *(const uint4*)(b_lo + boff);
            }
        }

#pragma unroll
        for (int kst = 0; kst < 2; kst++) {
            uint32_t ahi[2][4], alo[2][4];
#pragma unroll
            for (int mh = 0; mh < 2; mh++) {
                const int tile = lane >> 3;
                const int row = wm * 32 + mh * 16 + ((tile & 1) << 3) + (lane & 7);
                const int unit = kst * 2 + (tile >> 1);
                const uint32_t so = SWZ64((uint32_t)(row * 64 + unit * 16));
                ldsm4(ahi[mh], A_HI + so);
                ldsm4(alo[mh], A_LO + so);
            }
            uint32_t bhi[8][2], blo[8][2];
#pragma unroll
            for (int ng = 0; ng < 4; ng++) {
                const int tile = lane >> 3;
                const int row = wn * 64 + ng * 16 + ((tile >> 1) << 3) + (lane & 7);
                const int unit = kst * 2 + (tile & 1);
                const uint32_t so = SWZ64((uint32_t)(row * 64 + unit * 16));
                uint32_t th[4], tl[4];
                ldsm4(th, B_HI + so);
                ldsm4(tl, B_LO + so);
                bhi[ng * 2][0] = th[0]; bhi[ng * 2][1] = th[1];
                bhi[ng * 2 + 1][0] = th[2]; bhi[ng * 2 + 1][1] = th[3];
                blo[ng * 2][0] = tl[0]; blo[ng * 2][1] = tl[1];
                blo[ng * 2 + 1][0] = tl[2]; blo[ng * 2 + 1][1] = tl[3];
            }
#pragma unroll
            for (int mh = 0; mh < 2; mh++)
#pragma unroll
                for (int nt = 0; nt < 8; nt++) {
                    mma_bf16(acc[mh][nt], ahi[mh], bhi[nt]);
                    mma_bf16(acc[mh][nt], alo[mh], bhi[nt]);
                    mma_bf16(acc[mh][nt], ahi[mh], blo[nt]);
                }
        }
    }

    float* base = part + (size_t)z * NELEM;
#pragma unroll
    for (int mh = 0; mh < 2; mh++) {
        const int mrow = m0 + wm * 32 + mh * 16 + (lane >> 2);
#pragma unroll
        for (int nt = 0; nt < 8; nt++) {
            const int n = n0 + wn * 64 + nt * 8 + (lane & 3) * 2;
            *(float2*)&base[(size_t)mrow * Cc + n] =
                make_float2(acc[mh][nt][0], acc[mh][nt][1]);
            *(float2*)&base[(size_t)(mrow + 8) * Cc + n] =
                make_float2(acc[mh][nt][2], acc[mh][nt][3]);
        }
    }
}

// ---------------- decompose x into bf16 hi/lo ----------------
__global__ void decomp_x_kernel(const float* __restrict__ x,
                                __nv_bfloat16* __restrict__ hi, __nv_bfloat16* __restrict__ lo)
{
    const int i = blockIdx.x * blockDim.x + threadIdx.x;
    if (i < NELEM) {
        const float v = x[i];
        const __nv_bfloat16 h = __float2bfloat16(v);
        hi[i] = h;
        lo[i] = __float2bfloat16(v - __bfloat162float(h));
    }
}

// ---------------- decompose kvg = kp+vp into bf16 hi/lo ----------------
__global__ void decomp_kvg_kernel(const float* __restrict__ kp, const float* __restrict__ vp,
                                  __nv_bfloat16* __restrict__ hi, __nv_bfloat16* __restrict__ lo)
{
    const int i = blockIdx.x * blockDim.x + threadIdx.x;
    if (i < NELEM) {
        const float v = kp[i] + vp[i];
        const __nv_bfloat16 h = __float2bfloat16(v);
        hi[i] = h;
        lo[i] = __float2bfloat16(v - __bfloat162float(h));
    }
}

// ---------------- transpose + decompose conv weights: [6400,256] -> [256,6400] ----------------
__global__ void decomp_wt_kernel(const float* __restrict__ w,
                                 __nv_bfloat16* __restrict__ hi, __nv_bfloat16* __restrict__ lo)
{
    __shared__ float tile[32][33];
    const int k0 = blockIdx.x * 32;
    const int n0 = blockIdx.y * 32;
    const int tx = threadIdx.x, ty = threadIdx.y;
#pragma unroll
    for (int i = 0; i < 4; i++)
        tile[ty + i * 8][tx] = w[(long)(k0 + ty + i * 8) * Cc + n0 + tx];
    __syncthreads();
#pragma unroll
    for (int i = 0; i < 4; i++) {
        const float v = tile[tx][ty + i * 8];
        const __nv_bfloat16 h = __float2bfloat16(v);
        const long o = (long)(n0 + ty + i * 8) * KTOT + k0 + tx;
        hi[o] = h;
        lo[o] = __float2bfloat16(v - __bfloat162float(h));
    }
}

// ---------------- transpose + decompose 7 proj weights [256,256] -> [256,256]^T ----------------
struct W7 { const float* w[7]; };
__global__ void decomp_w7_kernel(W7 ws,
                                 __nv_bfloat16* __restrict__ hi, __nv_bfloat16* __restrict__ lo)
{
    __shared__ float tile[32][33];
    const int z  = blockIdx.z;
    const float* __restrict__ w = ws.w[z];
    const long zo = (long)z * Cc * Cc;
    const int k0 = blockIdx.x * 32;
    const int n0 = blockIdx.y * 32;
    const int tx = threadIdx.x, ty = threadIdx.y;
#pragma unroll
    for (int i = 0; i < 4; i++)
        tile[ty + i * 8][tx] = w[(long)(k0 + ty + i * 8) * Cc + n0 + tx];
    __syncthreads();
#pragma unroll
    for (int i = 0; i < 4; i++) {
        const float v = tile[tx][ty + i * 8];
        const __nv_bfloat16 h = __float2bfloat16(v);
        const long o = zo + (long)(n0 + ty + i * 8) * Cc + k0 + tx;
        hi[o] = h;
        lo[o] = __float2bfloat16(v - __bfloat162float(h));
    }
}

// ---------------- block mean pooling ----------------
__global__ void pool_kernel(const float* __restrict__ qp, const float* __restrict__ kp,
                            float* __restrict__ qloc, float* __restrict__ kloc)
{
    const int bp = blockIdx.x;
    const int c  = threadIdx.x;
    const float* qb = qp + (long)bp * LBLK * Cc + c;
    const float* kb = kp + (long)bp * LBLK * Cc + c;
    float sq = 0.f, sk = 0.f;
    for (int i = 0; i < LBLK; i++) { sq += qb[i * Cc]; sk += kb[i * Cc]; }
    qloc[bp * Cc + c] = sq * (1.f / (float)LBLK);
    kloc[bp * Cc + c] = sk * (1.f / (float)LBLK);
}

// ---------------- routing ----------------
__global__ void route_kernel(const float* __restrict__ qloc, const float* __restrict__ kloc,
                             int* __restrict__ R)
{
    const int bp = blockIdx.x;
    const int b  = bp / Pp;
    const int warp = threadIdx.x >> 5;
    const int lane = threadIdx.x & 31;
    __shared__ float s[8];
    const float* q = qloc + bp * Cc;
    const float* k = kloc + (b * Pp + warp) * Cc;
    float partial = 0.f;
    for (int c = lane; c < Cc; c += 32) partial += q[c] * k[c];
#pragma unroll
    for (int o = 16; o; o >>= 1) partial += __shfl_xor_sync(0xffffffff, partial, o);
    if (lane == 0) s[warp] = partial;
    __syncthreads();
    if (threadIdx.x == 0) {
        bool used[8] = {};
        for (int t = 0; t < KV; t++) {
            int best = 0; float bv = -1e30f;
            for (int j = 0; j < Pp; j++)
                if (!used[j] && s[j] > bv) { bv = s[j]; best = j; }
            used[best] = true;
            R[bp * KV + t] = best;
        }
    }
}

// ---------------- attention (writes ctx hi/lo for the wo tensor GEMM) ----------------
#define KCHUNK 128
__global__ void attention_kernel(const float* __restrict__ q2,
                                 const float* __restrict__ k2,
                                 const float* __restrict__ v2,
                                 const int* __restrict__ R,
                                 __nv_bfloat16* __restrict__ ctx_hi,
                                 __nv_bfloat16* __restrict__ ctx_lo)
{
    __shared__ float Ks[KCHUNK * DK];
    __shared__ float Vs[KCHUNK * DK];
    __shared__ int   Rs[KV];

    const int blk = blockIdx.x;
    const int h = blk % NHh;
    const int p = (blk / NHh) % Pp;
    const int b = blk / (NHh * Pp);
    const int tid = threadIdx.x;

    if (tid < KV) Rs[tid] = R[(b * Pp + p) * KV + tid];

    const bool active = (tid < LBLK);
    unsigned long long qv2[DK / 2], acc2[DK / 2];
    float m = -1e30f, l = 0.f;
    if (active) {
        const float* qrow = q2 + ((long)((b * Pp + p) * LBLK + tid)) * Cc + h * DK;
#pragma unroll
        for (int d2 = 0; d2 < DK / 2; d2++) {
            qv2[d2] = pk2(qrow[2 * d2] * QK_SCALE, qrow[2 * d2 + 1] * QK_SCALE);
            acc2[d2] = 0ull;
        }
    }

    for (int ch = 0; ch < LKEY / KCHUNK; ch++) {
        __syncthreads();
        const int kg0 = ch * KCHUNK;
        for (int i = tid; i < KCHUNK * (DK / 4); i += blockDim.x) {
            const int row = i >> 3;
            const int d4  = (i & 7) * 4;
            const int kg  = kg0 + row;
            const int ks  = kg / LBLK;
            const int rr  = kg - ks * LBLK;
            const int r   = Rs[ks];
            const long base = ((long)(b * Pp + r) * LBLK + rr) * Cc + h * DK + d4;
            *(float4*)&Ks[row * DK + d4] = *(const float4*)&k2[base];
            *(float4*)&Vs[row * DK + d4] = *(const float4*)&v2[base];
        }
        __syncthreads();
        if (active) {
            for (int k = 0; k < KCHUNK; k++) {
                const unsigned long long* kr = (const unsigned long long*)&Ks[k * DK];
                unsigned long long s0 = 0ull, s1 = 0ull, s2 = 0ull, s3 = 0ull;
#pragma unroll
                for (int d2 = 0; d2 < DK / 2; d2 += 4) {
                    s0 = ffma2(qv2[d2 + 0], kr[d2 + 0], s0);
                    s1 = ffma2(qv2[d2 + 1], kr[d2 + 1], s1);
                    s2 = ffma2(qv2[d2 + 2], kr[d2 + 2], s2);
                    s3 = ffma2(qv2[d2 + 3], kr[d2 + 3], s3);
                }
                const float2 f0 = upk2(s0), f1 = upk2(s1), f2 = upk2(s2), f3 = upk2(s3);
                const float s = ((f0.x + f0.y) + (f1.x + f1.y)) + ((f2.x + f2.y) + (f3.x + f3.y));
                const float mnew = fmaxf(m, s);
                const float corr = fast_exp2(m - mnew);
                const float pe   = fast_exp2(s - mnew);
                l = fmaf(l, corr, pe);
                const unsigned long long cc = pk2(corr, corr);
                const unsigned long long pp = pk2(pe, pe);
                const unsigned long long* vr = (const unsigned long long*)&Vs[k * DK];
#pragma unroll
                for (int d2 = 0; d2 < DK / 2; d2++)
                    acc2[d2] = ffma2(acc2[d2], cc, fmul2(pp, vr[d2]));
                m = mnew;
            }
        }
    }

    if (active) {
        const float inv = 1.0f / l;
        const long base = ((long)((b * Pp + p) * LBLK + tid)) * Cc + h * DK;
#pragma unroll
        for (int d2 = 0; d2 < DK / 2; d2++) {
            float2 f = upk2(acc2[d2]);
            const float v0 = f.x * inv, v1 = f.y * inv;
            const __nv_bfloat16 h0 = __float2bfloat16(v0);
            const __nv_bfloat16 h1 = __float2bfloat16(v1);
            *(__nv_bfloat162*)&ctx_hi[base + 2 * d2] = __nv_bfloat162(h0, h1);
            *(__nv_bfloat162*)&ctx_lo[base + 2 * d2] = __nv_bfloat162(
                __float2bfloat16(v0 - __bfloat162float(h0)),
                __float2bfloat16(v1 - __bfloat162float(h1)));
        }
    }
}

// ---------------- fused residual add + LayerNorm ----------------
__global__ void add_ln_kernel(const float* __restrict__ a, const float* __restrict__ bsrc,
                              const float* __restrict__ g, const float* __restrict__ beta,
                              float* __restrict__ out)
{
    const int mrow = blockIdx.x;
    const int c = threadIdx.x;
    __shared__ float red[Cc];
    const float v = a[(long)mrow * Cc + c] + bsrc[(long)mrow * Cc + c];
    red[c] = v;
    __syncthreads();
    for (int s = Cc / 2; s > 0; s >>= 1) {
        if (c < s) red[c] += red[c + s];
        __syncthreads();
    }
    const float mean = red[0] * (1.f / (float)Cc);
    __syncthreads();
    const float d = v - mean;
    red[c] = d * d;
    __syncthreads();
    for (int s = Cc / 2; s > 0; s >>= 1) {
        if (c < s) red[c] += red[c + s];
        __syncthreads();
    }
    const float var = red[0] * (1.f / (float)Cc);
    out[(long)mrow * Cc + c] = d * rsqrtf(var + 1e-5f) * g[c] + beta[c];
}

// xres + (sum of NSPLIT conv partials + conv bias) -> LN -> out
__global__ void add_lnK_kernel(const float* __restrict__ a, const float* __restrict__ pbase,
                               const float* __restrict__ cb,
                               const float* __restrict__ g, const float* __restrict__ beta,
                               float* __restrict__ out)
{
    const int mrow = blockIdx.x;
    const int c = threadIdx.x;
    __shared__ float red[Cc];
    const long off = (long)mrow * Cc + c;
    float v = a[off] + cb[c];
#pragma unroll
    for (int s = 0; s < NSPLIT; s++) v += pbase[off + (size_t)s * NELEM];
    red[c] = v;
    __syncthreads();
    for (int s = Cc / 2; s > 0; s >>= 1) {
        if (c < s) red[c] += red[c + s];
        __syncthreads();
    }
    const float mean = red[0] * (1.f / (float)Cc);
    __syncthreads();
    const float d = v - mean;
    red[c] = d * d;
    __syncthreads();
    for (int s = Cc / 2; s > 0; s >>= 1) {
        if (c < s) red[c] += red[c + s];
        __syncthreads();
    }
    const float var = red[0] * (1.f / (float)Cc);
    out[off] = d * rsqrtf(var + 1e-5f) * g[c] + beta[c];
}

// ---------------- launcher ----------------
extern "C" void kernel_launch(void* const* d_in, const int* in_sizes, int n_in,
                              void* d_out, int out_size)
{
    const float* x        = (const float*)d_in[0];
    const float* wq_proj  = (const float*)d_in[1];
    const float* bq_proj  = (const float*)d_in[2];
    const float* wk_proj  = (const float*)d_in[3];
    const float* bk_proj  = (const float*)d_in[4];
    const float* wv_proj  = (const float*)d_in[5];
    const float* bv_proj  = (const float*)d_in[6];
    const float* wq_a     = (const float*)d_in[7];
    const float* bq_a     = (const float*)d_in[8];
    const float* wk_a     = (const float*)d_in[9];
    const float* bk_a     = (const float*)d_in[10];
    const float* wv_a     = (const float*)d_in[11];
    const float* bv_a     = (const float*)d_in[12];
    const float* wo_a     = (const float*)d_in[13];
    const float* bo_a     = (const float*)d_in[14];
    const float* conv_w   = (const float*)d_in[15];
    const float* conv_b   = (const float*)d_in[16];
    const float* ln1_g    = (const float*)d_in[17];
    const float* ln1_b    = (const float*)d_in[18];
    const float* ln2_g    = (const float*)d_in[19];
    const float* ln2_b    = (const float*)d_in[20];
    float* out = (float*)d_out;

    float* buf = nullptr;       cudaGetSymbolAddress((void**)&buf, g_buf);
    float* loc = nullptr;       cudaGetSymbolAddress((void**)&loc, g_loc);
    int*   Rp  = nullptr;       cudaGetSymbolAddress((void**)&Rp, g_R);
    __nv_bfloat16 *xh, *xl, *ah, *al, *cxh, *cxl, *kvh, *kvl, *wth, *wtl, *w7h, *w7l;
    cudaGetSymbolAddress((void**)&xh,  g_x_hi);
    cudaGetSymbolAddress((void**)&xl,  g_x_lo);
    cudaGetSymbolAddress((void**)&ah,  g_act_hi);
    cudaGetSymbolAddress((void**)&al,  g_act_lo);
    cudaGetSymbolAddress((void**)&cxh, g_ctx_hi);
    cudaGetSymbolAddress((void**)&cxl, g_ctx_lo);
    cudaGetSymbolAddress((void**)&kvh, g_kvg_hi);
    cudaGetSymbolAddress((void**)&kvl, g_kvg_lo);
    cudaGetSymbolAddress((void**)&wth, g_wt_hi);
    cudaGetSymbolAddress((void**)&wtl, g_wt_lo);
    cudaGetSymbolAddress((void**)&w7h, g_w7_hi);
    cudaGetSymbolAddress((void**)&w7l, g_w7_lo);

    float* qp   = buf + 0l * NELEM;
    float* kp   = buf + 1l * NELEM;
    float* vp   = buf + 2l * NELEM;
    float* xres = buf + 3l * NELEM;
    float* q2   = buf + 4l * NELEM;
    float* k2   = buf + 5l * NELEM;
    float* v2   = buf + 6l * NELEM;
    float* rout = buf + 7l * NELEM;
    float* cnvp = buf + 8l * NELEM;
    float* qloc = loc;
    float* kloc = loc + 16 * Cc;

    const long WSZ = (long)Cc * Cc;

    // 1: transpose+decompose 7 projection weights
    {
        W7 ws;
        ws.w[0] = wq_proj; ws.w[1] = wk_proj; ws.w[2] = wv_proj;
        ws.w[3] = wq_a;    ws.w[4] = wk_a;    ws.w[5] = wv_a;
        ws.w[6] = wo_a;
        decomp_w7_kernel<<<dim3(Cc / 32, Cc / 32, 7), dim3(32, 8)>>>(ws, w7h, w7l);
    }

    // 2: conv weight transpose+decompose
    decomp_wt_kernel<<<dim3(KTOT / 32, Cc / 32), dim3(32, 8)>>>(conv_w, wth, wtl);

    // 3: x decompose
    decomp_x_kernel<<<NELEM / 256, 256>>>(x, xh, xl);

    // 4: q/k/v block projections (tensor, profiled slot)
    {
        GemmSetT gs;
        for (int i = 0; i < 3; i++) {
            gs.Ah[i] = xh; gs.Al[i] = xl;
            gs.Bh[i] = w7h + i * WSZ; gs.Bl[i] = w7l + i * WSZ;
            gs.Ch[i] = ah + (long)i * NELEM; gs.Cl[i] = al + (long)i * NELEM;
        }
        gs.bias[0] = bq_proj; gs.bias[1] = bk_proj; gs.bias[2] = bv_proj;
        gs.C[0] = qp; gs.C[1] = kp; gs.C[2] = vp;
        gemm_mma_kernel<<<dim3(NROW / 128, Cc / 128, 3), 256>>>(gs);
    }

    // 5: conv input decompose (k_p + v_p)
    decomp_kvg_kernel<<<NELEM / 256, 256>>>(kp, vp, kvh, kvl);

    // 6: conv via pipelined mma.sync
    conv_mma_kernel<<<dim3(NROW / 128, Cc / 128, NSPLIT), 256>>>(kvh, kvl, wth, wtl, cnvp);

    // 7-8: routing
    pool_kernel<<<Bsz * Pp, Cc>>>(qp, kp, qloc, kloc);
    route_kernel<<<Bsz * Pp, 256>>>(qloc, kloc, Rp);

    // 9: attention head projections (tensor)
    {
        GemmSetT gs;
        for (int i = 0; i < 3; i++) {
            gs.Ah[i] = ah + (long)i * NELEM; gs.Al[i] = al + (long)i * NELEM;
            gs.Bh[i] = w7h + (3 + i) * WSZ;  gs.Bl[i] = w7l + (3 + i) * WSZ;
            gs.Ch[i] = nullptr; gs.Cl[i] = nullptr;
        }
        gs.bias[0] = bq_a; gs.bias[1] = bk_a; gs.bias[2] = bv_a;
        gs.C[0] = q2; gs.C[1] = k2; gs.C[2] = v2;
        gemm_mma_kernel<<<dim3(NROW / 128, Cc / 128, 3), 256>>>(gs);
    }

    // 10: routed attention (emits ctx hi/lo)
    attention_kernel<<<Bsz * Pp * NHh, 256>>>(q2, k2, v2, Rp, cxh, cxl);

    // 11: output projection (tensor, single matrix)
    {
        GemmSetT gs;
        gs.Ah[0] = cxh; gs.Al[0] = cxl;
        gs.Bh[0] = w7h + 6 * WSZ; gs.Bl[0] = w7l + 6 * WSZ;
        gs.bias[0] = bo_a;
        gs.C[0] = rout;
        gs.Ch[0] = nullptr; gs.Cl[0] = nullptr;
        for (int i = 1; i < 3; i++) {
            gs.Ah[i] = cxh; gs.Al[i] = cxl;
            gs.Bh[i] = w7h; gs.Bl[i] = w7l;
            gs.bias[i] = bo_a; gs.C[i] = rout;
            gs.Ch[i] = nullptr; gs.Cl[i] = nullptr;
        }
        gemm_mma_kernel<<<dim3(NROW / 128, Cc / 128, 1), 256>>>(gs);
    }

    // 12-13: LayerNorms
    add_ln_kernel<<<NROW, Cc>>>(x, rout, ln1_g, ln1_b, xres);
    add_lnK_kernel<<<NROW, Cc>>>(xres, cnvp, conv_b, ln2_g, ln2_b, out);
}